// round 6
// baseline (speedup 1.0000x reference)
#include <cuda_runtime.h>
#include <cuda_bf16.h>
#include <cstdint>

#define B_  16
#define N_  1024
#define S_  256
#define D_  1024
#define HQ  16
#define HKV 8
#define HD  64
#define KVE 512

// ---------------- scratch (device globals; no cudaMalloc allowed) ----------
__device__ int8_t g_xq [(size_t)B_*N_*D_];
__device__ int8_t g_yq [(size_t)B_*S_*D_];
__device__ int8_t g_a2q[(size_t)B_*N_*D_];
__device__ int8_t g_wqt[D_*D_];
__device__ int8_t g_wkt[KVE*D_];
__device__ int8_t g_wvt[KVE*D_];
__device__ int8_t g_wot[D_*D_];
// hi/lo bf16 planes for q/k/v (exact fp32 split)
__device__ __nv_bfloat16 g_qh[(size_t)B_*N_*D_];
__device__ __nv_bfloat16 g_ql[(size_t)B_*N_*D_];
__device__ __nv_bfloat16 g_kh[(size_t)B_*S_*KVE];
__device__ __nv_bfloat16 g_kl[(size_t)B_*S_*KVE];
__device__ __nv_bfloat16 g_vh[(size_t)B_*S_*KVE];
__device__ __nv_bfloat16 g_vl[(size_t)B_*S_*KVE];
__device__ float  g_att[(size_t)B_*N_*D_];
__device__ float  g_rfx[B_*N_];
__device__ float  g_rfy[B_*S_];
__device__ float  g_rf2[B_*N_];
__device__ double g_part[4*256];
__device__ double g_wsum[4];

// ---------------- fused block reductions (256 threads) ----------------------
__device__ __forceinline__ float block_sum(float v, float* sbuf) {
    #pragma unroll
    for (int o = 16; o; o >>= 1) v += __shfl_xor_sync(0xffffffffu, v, o);
    int w = threadIdx.x >> 5, l = threadIdx.x & 31;
    if (!l) sbuf[w] = v;
    __syncthreads();
    if (threadIdx.x < 8) {
        v = sbuf[threadIdx.x];
        #pragma unroll
        for (int o = 4; o; o >>= 1) v += __shfl_xor_sync(0x000000ffu, v, o);
        if (!threadIdx.x) sbuf[0] = v;
    }
    __syncthreads();
    v = sbuf[0];
    __syncthreads();
    return v;
}
// simultaneous (sum, max)
__device__ __forceinline__ void block_summax(float& s, float& m, float* sbuf) {
    #pragma unroll
    for (int o = 16; o; o >>= 1) {
        s += __shfl_xor_sync(0xffffffffu, s, o);
        m = fmaxf(m, __shfl_xor_sync(0xffffffffu, m, o));
    }
    int w = threadIdx.x >> 5, l = threadIdx.x & 31;
    if (!l) { sbuf[w] = s; sbuf[8 + w] = m; }
    __syncthreads();
    if (threadIdx.x < 8) {
        s = sbuf[threadIdx.x];
        m = sbuf[8 + threadIdx.x];
        #pragma unroll
        for (int o = 4; o; o >>= 1) {
            s += __shfl_xor_sync(0x000000ffu, s, o);
            m = fmaxf(m, __shfl_xor_sync(0x000000ffu, m, o));
        }
        if (!threadIdx.x) { sbuf[0] = s; sbuf[8] = m; }
    }
    __syncthreads();
    s = sbuf[0]; m = sbuf[8];
    __syncthreads();
}
// simultaneous (sum, sum)
__device__ __forceinline__ void block_sum2(float& a, float& b, float* sbuf) {
    #pragma unroll
    for (int o = 16; o; o >>= 1) {
        a += __shfl_xor_sync(0xffffffffu, a, o);
        b += __shfl_xor_sync(0xffffffffu, b, o);
    }
    int w = threadIdx.x >> 5, l = threadIdx.x & 31;
    if (!l) { sbuf[w] = a; sbuf[8 + w] = b; }
    __syncthreads();
    if (threadIdx.x < 8) {
        a = sbuf[threadIdx.x];
        b = sbuf[8 + threadIdx.x];
        #pragma unroll
        for (int o = 4; o; o >>= 1) {
            a += __shfl_xor_sync(0x000000ffu, a, o);
            b += __shfl_xor_sync(0x000000ffu, b, o);
        }
        if (!threadIdx.x) { sbuf[0] = a; sbuf[8] = b; }
    }
    __syncthreads();
    a = sbuf[0]; b = sbuf[8];
    __syncthreads();
}

// ---------------- weight prep (fused) ----------------------------------------
__global__ void __launch_bounds__(256) absmean_all_kernel(const float* __restrict__ w0,
    const float* __restrict__ w1, const float* __restrict__ w2, const float* __restrict__ w3) {
    __shared__ float sbuf[16];
    int slot = blockIdx.y;
    const float* w = slot == 0 ? w0 : slot == 1 ? w1 : slot == 2 ? w2 : w3;
    int n = (slot == 1 || slot == 2) ? KVE * D_ : D_ * D_;
    float s = 0.f;
    for (int i = blockIdx.x * 256 + threadIdx.x; i < n; i += 256 * 256)
        s += fabsf(w[i]);
    s = block_sum(s, sbuf);
    if (!threadIdx.x) g_part[slot * 256 + blockIdx.x] = (double)s;
}
__global__ void __launch_bounds__(256) reduce_kernel() {
    __shared__ double sd[256];
    int slot = blockIdx.x;
    sd[threadIdx.x] = g_part[slot * 256 + threadIdx.x];
    __syncthreads();
    for (int o = 128; o; o >>= 1) {
        if (threadIdx.x < o) sd[threadIdx.x] += sd[threadIdx.x + o];
        __syncthreads();
    }
    if (!threadIdx.x) g_wsum[slot] = sd[0];
}
__global__ void __launch_bounds__(256) wquant_all_kernel(const float* __restrict__ w0,
    const float* __restrict__ w1, const float* __restrict__ w2, const float* __restrict__ w3) {
    int slot = blockIdx.y;
    const float* w = slot == 0 ? w0 : slot == 1 ? w1 : slot == 2 ? w2 : w3;
    int8_t* out = slot == 0 ? g_wqt : slot == 1 ? g_wkt : slot == 2 ? g_wvt : g_wot;
    int n = (slot == 1 || slot == 2) ? KVE * D_ : D_ * D_;
    double invcnt = 1.0 / (double)n;
    float mean  = (float)(g_wsum[slot] * invcnt);
    float scale = 1.0f / fmaxf(mean, 1e-5f);
    for (int i = blockIdx.x * 256 + threadIdx.x; i < n; i += gridDim.x * 256) {
        float t = fminf(fmaxf(rintf(w[i] * scale), -1.f), 1.f);
        out[i] = (int8_t)t;
    }
}

// ---------------- activation quant (x and y fused, int8 out) ----------------
__global__ void __launch_bounds__(256) act_quant_kernel(const float* __restrict__ X,
                                                        const float* __restrict__ Y) {
    __shared__ float sbuf[16];
    int which = blockIdx.x >= B_ * N_;
    size_t row = which ? blockIdx.x - B_ * N_ : blockIdx.x;
    const float* src = which ? Y : X;
    int8_t* Q  = which ? g_yq : g_xq;
    float*  RF = which ? g_rfy : g_rfx;
    int t = threadIdx.x;
    float4 xv = ((const float4*)(src + row * D_))[t];

    float ssq = xv.x*xv.x + xv.y*xv.y + xv.z*xv.z + xv.w*xv.w;
    float am  = fmaxf(fmaxf(fabsf(xv.x), fabsf(xv.y)), fmaxf(fabsf(xv.z), fabsf(xv.w)));
    block_summax(ssq, am, sbuf);
    float r = 1.0f / sqrtf(ssq * (1.0f/1024.0f) + 1e-6f);
    am *= r;
    float sc = 127.0f / fmaxf(am, 1e-5f);

    char4 c4;
    c4.x = (signed char)fminf(fmaxf(rintf((xv.x*r)*sc), -128.f), 127.f);
    c4.y = (signed char)fminf(fmaxf(rintf((xv.y*r)*sc), -128.f), 127.f);
    c4.z = (signed char)fminf(fmaxf(rintf((xv.z*r)*sc), -128.f), 127.f);
    c4.w = (signed char)fminf(fmaxf(rintf((xv.w*r)*sc), -128.f), 127.f);
    *(char4*)(Q + row * D_ + t * 4) = c4;
    if (!t) RF[row] = 1.0f / sc;
}

// ---------------- fused LayerNorm + rms_norm + act_quant (int8 out) --------
__global__ void __launch_bounds__(256) ln_quant_kernel(const float* __restrict__ gamma,
                                                       const float* __restrict__ beta) {
    __shared__ float sbuf[16];
    size_t row = blockIdx.x;
    int t = threadIdx.x;
    float4 xv = ((const float4*)(g_att + row * D_))[t];

    float s  = xv.x + xv.y + xv.z + xv.w;
    float sq = xv.x*xv.x + xv.y*xv.y + xv.z*xv.z + xv.w*xv.w;
    block_sum2(s, sq, sbuf);
    float mu  = s * (1.0f/1024.0f);
    float var = sq * (1.0f/1024.0f) - mu * mu;
    float rs  = 1.0f / sqrtf(var + 1e-5f);

    float4 gv = ((const float4*)gamma)[t];
    float4 bv = ((const float4*)beta)[t];
    float y0 = ((xv.x-mu)*rs)*gv.x + bv.x, y1 = ((xv.y-mu)*rs)*gv.y + bv.y;
    float y2 = ((xv.z-mu)*rs)*gv.z + bv.z, y3 = ((xv.w-mu)*rs)*gv.w + bv.w;

    float m2 = y0*y0 + y1*y1 + y2*y2 + y3*y3;
    float am = fmaxf(fmaxf(fabsf(y0), fabsf(y1)), fmaxf(fabsf(y2), fabsf(y3)));
    block_summax(m2, am, sbuf);
    float r2 = 1.0f / sqrtf(m2 * (1.0f/1024.0f) + 1e-6f);
    am *= r2;
    float sc = 127.0f / fmaxf(am, 1e-5f);

    char4 c4;
    c4.x = (signed char)fminf(fmaxf(rintf((y0*r2)*sc), -128.f), 127.f);
    c4.y = (signed char)fminf(fmaxf(rintf((y1*r2)*sc), -128.f), 127.f);
    c4.z = (signed char)fminf(fmaxf(rintf((y2*r2)*sc), -128.f), 127.f);
    c4.w = (signed char)fminf(fmaxf(rintf((y3*r2)*sc), -128.f), 127.f);
    *(char4*)(g_a2q + row * D_ + t * 4) = c4;
    if (!t) g_rf2[row] = 1.0f / sc;
}

// ---------------- mma / ldmatrix / cp.async helpers -------------------------
__device__ __forceinline__ void ldsm4(uint32_t (&r)[4], uint32_t a) {
    asm volatile("ldmatrix.sync.aligned.m8n8.x4.shared.b16 {%0,%1,%2,%3}, [%4];"
                 : "=r"(r[0]), "=r"(r[1]), "=r"(r[2]), "=r"(r[3]) : "r"(a));
}
__device__ __forceinline__ void ldsm4t(uint32_t (&r)[4], uint32_t a) {
    asm volatile("ldmatrix.sync.aligned.m8n8.x4.trans.shared.b16 {%0,%1,%2,%3}, [%4];"
                 : "=r"(r[0]), "=r"(r[1]), "=r"(r[2]), "=r"(r[3]) : "r"(a));
}
__device__ __forceinline__ void mma_bf16(float (&d)[4], const uint32_t (&a)[4],
                                         uint32_t b0, uint32_t b1) {
    asm volatile("mma.sync.aligned.m16n8k16.row.col.f32.bf16.bf16.f32 "
                 "{%0,%1,%2,%3}, {%4,%5,%6,%7}, {%8,%9}, {%0,%1,%2,%3};"
                 : "+f"(d[0]), "+f"(d[1]), "+f"(d[2]), "+f"(d[3])
                 : "r"(a[0]), "r"(a[1]), "r"(a[2]), "r"(a[3]), "r"(b0), "r"(b1));
}
__device__ __forceinline__ void mma_s8(int (&d)[4], const uint32_t (&a)[4],
                                       uint32_t b0, uint32_t b1) {
    asm volatile("mma.sync.aligned.m16n8k32.row.col.s32.s8.s8.s32 "
                 "{%0,%1,%2,%3}, {%4,%5,%6,%7}, {%8,%9}, {%0,%1,%2,%3};"
                 : "+r"(d[0]), "+r"(d[1]), "+r"(d[2]), "+r"(d[3])
                 : "r"(a[0]), "r"(a[1]), "r"(a[2]), "r"(a[3]), "r"(b0), "r"(b1));
}
__device__ __forceinline__ void cpa16(uint32_t s, const void* g) {
    asm volatile("cp.async.cg.shared.global [%0], [%1], 16;" :: "r"(s), "l"(g));
}
#define CP_COMMIT asm volatile("cp.async.commit_group;")
#define CP_WAIT2  asm volatile("cp.async.wait_group 2;")
#define CP_WAIT0  asm volatile("cp.async.wait_group 0;")

__device__ __forceinline__ uint32_t pack_hl(float x, float y, uint32_t& lo) {
    __nv_bfloat16 hx = __float2bfloat16(x), hy = __float2bfloat16(y);
    __nv_bfloat16 lx = __float2bfloat16(x - __bfloat162float(hx));
    __nv_bfloat16 ly = __float2bfloat16(y - __bfloat162float(hy));
    lo = ((uint32_t)__bfloat16_as_ushort(ly) << 16) | __bfloat16_as_ushort(lx);
    return ((uint32_t)__bfloat16_as_ushort(hy) << 16) | __bfloat16_as_ushort(hx);
}

// ---------------- exact integer GEMM via IMMA s8 (4-stage cp.async) --------
// A: [M,1024] s8, W: [N,1024] s8 ternary. tile 128x128, k-chunk 64 int8/stage.
// smem row stride 80B (64B data + 16B pad). Stage: A 10240B + B 10240B.
#define GI_SMEM (4 * 10240 * 2)
template<int MODE>   // 0: fp32 C; 1: hi/lo bf16 planes
__device__ __forceinline__ void gemm_i8(const int8_t* __restrict__ A,
                                        const int8_t* __restrict__ W,
                                        float* __restrict__ C,
                                        __nv_bfloat16* __restrict__ Ch,
                                        __nv_bfloat16* __restrict__ Cl,
                                        const float* __restrict__ rowf,
                                        int slot, double invcnt, float extra, int Nn) {
    extern __shared__ char smg[];
    const int K = 1024, T = 16;
    int tid = threadIdx.x, lane = tid & 31, w = tid >> 5;
    int warpM = w & 1, warpN = w >> 1;            // 2 x 4 warps -> 64x32 per warp
    int m0 = blockIdx.y * 128, n0 = blockIdx.x * 128;

    int acc[4][4][4];
    #pragma unroll
    for (int a = 0; a < 4; a++)
        #pragma unroll
        for (int b = 0; b < 4; b++)
            #pragma unroll
            for (int c = 0; c < 4; c++) acc[a][b][c] = 0;

    uint32_t sAb = (uint32_t)__cvta_generic_to_shared(smg);
    uint32_t sBb = sAb + 4 * 10240;
    int aRow = warpM * 64 + (lane & 15);
    int bRow = warpN * 32 + (lane & 15);
    int half = (lane >> 4) * 16;                   // byte offset of k-half

    #define GLOADI(t, buf) do {                                                \
        uint32_t bo = (uint32_t)(buf) * 10240u;                                \
        int k0 = (t) * 64;                                                     \
        _Pragma("unroll")                                                      \
        for (int i = 0; i < 2; i++) {                                          \
            int idx = tid + i * 256;                                           \
            int r = idx >> 2, c = (idx & 3) * 16;                              \
            cpa16(sAb + bo + (uint32_t)(r * 80 + c),                           \
                  A + (size_t)(m0 + r) * K + k0 + c);                          \
            cpa16(sBb + bo + (uint32_t)(r * 80 + c),                           \
                  W + (size_t)(n0 + r) * K + k0 + c);                          \
        }                                                                      \
    } while (0)

    GLOADI(0, 0); CP_COMMIT;
    GLOADI(1, 1); CP_COMMIT;
    GLOADI(2, 2); CP_COMMIT;

    #pragma unroll 1
    for (int t = 0; t < T; t++) {
        CP_WAIT2;
        __syncthreads();
        if (t + 3 < T) GLOADI(t + 3, (t + 3) & 3);
        CP_COMMIT;
        uint32_t bo = (uint32_t)(t & 3) * 10240u;
        #pragma unroll
        for (int kk = 0; kk < 2; kk++) {
            uint32_t af[4][4];
            #pragma unroll
            for (int mi = 0; mi < 4; mi++)
                ldsm4(af[mi], sAb + bo + (uint32_t)((aRow + mi * 16) * 80 + kk * 32 + half));
            uint32_t bf[2][4];
            #pragma unroll
            for (int nb = 0; nb < 2; nb++)
                ldsm4(bf[nb], sBb + bo + (uint32_t)((bRow + nb * 16) * 80 + kk * 32 + half));
            #pragma unroll
            for (int mi = 0; mi < 4; mi++)
                #pragma unroll
                for (int ni = 0; ni < 4; ni++)
                    mma_s8(acc[mi][ni], af[mi],
                           bf[ni >> 1][ni & 1], bf[ni >> 1][(ni & 1) + 2]);
        }
        __syncthreads();
    }
    #undef GLOADI

    float wf = fmaxf((float)(g_wsum[slot] * invcnt), 1e-5f);
    float sgl = wf * extra;
    #pragma unroll
    for (int mi = 0; mi < 4; mi++) {
        int m = m0 + warpM * 64 + mi * 16 + (lane >> 2);
        float f0 = rowf[m] * sgl, f1 = rowf[m + 8] * sgl;
        #pragma unroll
        for (int ni = 0; ni < 4; ni++) {
            int n = n0 + warpN * 32 + ni * 8 + (lane & 3) * 2;
            float v0 = (float)acc[mi][ni][0] * f0, v1 = (float)acc[mi][ni][1] * f0;
            float v2 = (float)acc[mi][ni][2] * f1, v3 = (float)acc[mi][ni][3] * f1;
            if (MODE == 0) {
                *(float2*)(C + (size_t)m * Nn + n)       = make_float2(v0, v1);
                *(float2*)(C + (size_t)(m + 8) * Nn + n) = make_float2(v2, v3);
            } else {
                uint32_t lo0, lo1;
                uint32_t hi0 = pack_hl(v0, v1, lo0);
                uint32_t hi1 = pack_hl(v2, v3, lo1);
                *(uint32_t*)(Ch + (size_t)m * Nn + n) = hi0;
                *(uint32_t*)(Cl + (size_t)m * Nn + n) = lo0;
                *(uint32_t*)(Ch + (size_t)(m + 8) * Nn + n) = hi1;
                *(uint32_t*)(Cl + (size_t)(m + 8) * Nn + n) = lo1;
            }
        }
    }
}

__global__ void __launch_bounds__(256) gemm_q_kernel() {
    gemm_i8<1>(g_xq, g_wqt, nullptr, g_qh, g_ql, g_rfx, 0, 1.0/(1024.0*1024.0), 0.125f, D_);
}
__global__ void __launch_bounds__(256) gemm_kv_kernel() {
    if (blockIdx.z == 0)
        gemm_i8<1>(g_yq, g_wkt, nullptr, g_kh, g_kl, g_rfy, 1, 1.0/(512.0*1024.0), 1.0f, KVE);
    else
        gemm_i8<1>(g_yq, g_wvt, nullptr, g_vh, g_vl, g_rfy, 2, 1.0/(512.0*1024.0), 1.0f, KVE);
}
__global__ void __launch_bounds__(256) gemm_o_kernel(float* __restrict__ out) {
    gemm_i8<0>(g_a2q, g_wot, out, nullptr, nullptr, g_rf2, 3, 1.0/(1024.0*1024.0), 1.0f, D_);
}

// ---------------- attention: hi/lo-split bf16 MMA (fp32-accurate) ----------
#define ATT_SMEM ((2 * 256 * 72 + 2 * 64 * 72) * 2)

__global__ void __launch_bounds__(128) attn_mma_kernel() {
    extern __shared__ __nv_bfloat16 sm[];
    __nv_bfloat16* sKVh = sm;
    __nv_bfloat16* sKVl = sm + 256 * 72;
    __nv_bfloat16* sQh  = sm + 2 * 256 * 72;
    __nv_bfloat16* sQl  = sQh + 64 * 72;

    int tid = threadIdx.x, lane = tid & 31, w = tid >> 5;
    int blk = blockIdx.x;
    int qt = blk & 15, qh = (blk >> 4) & 15, b = blk >> 8;
    int h = qh >> 1;

    uint32_t sQhB  = (uint32_t)__cvta_generic_to_shared(sQh);
    uint32_t sQlB  = (uint32_t)__cvta_generic_to_shared(sQl);
    uint32_t sKVhB = (uint32_t)__cvta_generic_to_shared(sKVh);
    uint32_t sKVlB = (uint32_t)__cvta_generic_to_shared(sKVl);

    const __nv_bfloat16* Qh = g_qh + ((size_t)(b * N_ + qt * 64)) * D_ + qh * HD;
    const __nv_bfloat16* Ql = g_ql + ((size_t)(b * N_ + qt * 64)) * D_ + qh * HD;
    const __nv_bfloat16* Kh = g_kh + (size_t)b * S_ * KVE + h * HD;
    const __nv_bfloat16* Kl = g_kl + (size_t)b * S_ * KVE + h * HD;
    const __nv_bfloat16* Vh = g_vh + (size_t)b * S_ * KVE + h * HD;
    const __nv_bfloat16* Vl = g_vl + (size_t)b * S_ * KVE + h * HD;

    #pragma unroll
    for (int i = tid; i < 512; i += 128) {
        int r = i >> 3, c = (i & 7) * 16;
        cpa16(sQhB + (uint32_t)(r * 144 + c), Qh + (size_t)r * D_ + c / 2);
        cpa16(sQlB + (uint32_t)(r * 144 + c), Ql + (size_t)r * D_ + c / 2);
    }
    #pragma unroll
    for (int i = tid; i < 2048; i += 128) {
        int r = i >> 3, c = (i & 7) * 16;
        cpa16(sKVhB + (uint32_t)(r * 144 + c), Kh + (size_t)r * KVE + c / 2);
        cpa16(sKVlB + (uint32_t)(r * 144 + c), Kl + (size_t)r * KVE + c / 2);
    }
    CP_COMMIT;
    CP_WAIT0;
    __syncthreads();

    int arow = w * 16 + (lane & 15);
    int acb  = (lane & 16) >> 1;
    uint32_t qhf[4][4], qlf[4][4];
    #pragma unroll
    for (int kt = 0; kt < 4; kt++) {
        uint32_t off = (uint32_t)((arow * 72 + kt * 16 + acb) * 2);
        ldsm4(qhf[kt], sQhB + off);
        ldsm4(qlf[kt], sQlB + off);
    }

    float c[32][4];
    #pragma unroll
    for (int i = 0; i < 32; i++)
        #pragma unroll
        for (int j = 0; j < 4; j++) c[i][j] = 0.f;

    int brow = (lane & 7) + ((lane & 16) >> 1);
    int bcol = lane & 8;
    #pragma unroll
    for (int np = 0; np < 16; np++) {
        #pragma unroll
        for (int kt = 0; kt < 4; kt++) {
            uint32_t off = (uint32_t)(((np * 16 + brow) * 72 + kt * 16 + bcol) * 2);
            uint32_t bh[4], bl[4];
            ldsm4(bh, sKVhB + off);
            ldsm4(bl, sKVlB + off);
            mma_bf16(c[2*np  ], qhf[kt], bh[0], bh[1]);
            mma_bf16(c[2*np  ], qhf[kt], bl[0], bl[1]);
            mma_bf16(c[2*np  ], qlf[kt], bh[0], bh[1]);
            mma_bf16(c[2*np+1], qhf[kt], bh[2], bh[3]);
            mma_bf16(c[2*np+1], qhf[kt], bl[2], bl[3]);
            mma_bf16(c[2*np+1], qlf[kt], bh[2], bh[3]);
        }
    }
    __syncthreads();

    #pragma unroll
    for (int i = tid; i < 2048; i += 128) {
        int r = i >> 3, cc = (i & 7) * 16;
        cpa16(sKVhB + (uint32_t)(r * 144 + cc), Vh + (size_t)r * KVE + cc / 2);
        cpa16(sKVlB + (uint32_t)(r * 144 + cc), Vl + (size_t)r * KVE + cc / 2);
    }
    CP_COMMIT;

    float mx0 = -1e30f, mx1 = -1e30f;
    #pragma unroll
    for (int nt = 0; nt < 32; nt++) {
        mx0 = fmaxf(mx0, fmaxf(c[nt][0], c[nt][1]));
        mx1 = fmaxf(mx1, fmaxf(c[nt][2], c[nt][3]));
    }
    mx0 = fmaxf(mx0, __shfl_xor_sync(0xffffffffu, mx0, 1));
    mx0 = fmaxf(mx0, __shfl_xor_sync(0xffffffffu, mx0, 2));
    mx1 = fmaxf(mx1, __shfl_xor_sync(0xffffffffu, mx1, 1));
    mx1 = fmaxf(mx1, __shfl_xor_sync(0xffffffffu, mx1, 2));
    float s0 = 0.f, s1 = 0.f;
    #pragma unroll
    for (int nt = 0; nt < 32; nt++) {
        c[nt][0] = __expf(c[nt][0] - mx0); s0 += c[nt][0];
        c[nt][1] = __expf(c[nt][1] - mx0); s0 += c[nt][1];
        c[nt][2] = __expf(c[nt][2] - mx1); s1 += c[nt][2];
        c[nt][3] = __expf(c[nt][3] - mx1); s1 += c[nt][3];
    }
    s0 += __shfl_xor_sync(0xffffffffu, s0, 1);
    s0 += __shfl_xor_sync(0xffffffffu, s0, 2);
    s1 += __shfl_xor_sync(0xffffffffu, s1, 1);
    s1 += __shfl_xor_sync(0xffffffffu, s1, 2);
    float i0 = 1.0f / s0, i1 = 1.0f / s1;
    #pragma unroll
    for (int nt = 0; nt < 32; nt++) {
        c[nt][0] *= i0; c[nt][1] *= i0; c[nt][2] *= i1; c[nt][3] *= i1;
    }
    CP_WAIT0;
    __syncthreads();

    float o[8][4];
    #pragma unroll
    for (int i = 0; i < 8; i++)
        #pragma unroll
        for (int j = 0; j < 4; j++) o[i][j] = 0.f;

    int vrow = (lane & 7) + (lane & 8);
    int vcb  = (lane & 16) >> 1;
    #pragma unroll
    for (int kt = 0; kt < 16; kt++) {
        uint32_t phi[4], plo[4];
        phi[0] = pack_hl(c[2*kt  ][0], c[2*kt  ][1], plo[0]);
        phi[1] = pack_hl(c[2*kt  ][2], c[2*kt  ][3], plo[1]);
        phi[2] = pack_hl(c[2*kt+1][0], c[2*kt+1][1], plo[2]);
        phi[3] = pack_hl(c[2*kt+1][2], c[2*kt+1][3], plo[3]);
        #pragma unroll
        for (int dp = 0; dp < 4; dp++) {
            uint32_t off = (uint32_t)(((kt * 16 + vrow) * 72 + dp * 16 + vcb) * 2);
            uint32_t bh[4], bl[4];
            ldsm4t(bh, sKVhB + off);
            ldsm4t(bl, sKVlB + off);
            mma_bf16(o[2*dp  ], phi, bh[0], bh[1]);
            mma_bf16(o[2*dp  ], phi, bl[0], bl[1]);
            mma_bf16(o[2*dp  ], plo, bh[0], bh[1]);
            mma_bf16(o[2*dp+1], phi, bh[2], bh[3]);
            mma_bf16(o[2*dp+1], phi, bl[2], bl[3]);
            mma_bf16(o[2*dp+1], plo, bh[2], bh[3]);
        }
    }

    float* Ob = g_att + ((size_t)(b * N_ + qt * 64 + w * 16 + (lane >> 2))) * D_ + qh * HD;
    #pragma unroll
    for (int nt = 0; nt < 8; nt++) {
        int col = nt * 8 + (lane & 3) * 2;
        *(float2*)(Ob + col)          = make_float2(o[nt][0], o[nt][1]);
        *(float2*)(Ob + 8 * D_ + col) = make_float2(o[nt][2], o[nt][3]);
    }
}

// ---------------- launch ----------------------------------------------------
extern "C" void kernel_launch(void* const* d_in, const int* in_sizes, int n_in,
                              void* d_out, int out_size) {
    const float* x  = (const float*)d_in[0];
    const float* y  = (const float*)d_in[1];
    const float* wq = (const float*)d_in[2];
    const float* wk = (const float*)d_in[3];
    const float* wv = (const float*)d_in[4];
    const float* wo = (const float*)d_in[5];
    const float* gamma = (const float*)d_in[6];
    const float* beta  = (const float*)d_in[7];
    float* out = (float*)d_out;

    cudaFuncSetAttribute(attn_mma_kernel,
                         cudaFuncAttributeMaxDynamicSharedMemorySize, ATT_SMEM);
    cudaFuncSetAttribute(gemm_q_kernel,  cudaFuncAttributeMaxDynamicSharedMemorySize, GI_SMEM);
    cudaFuncSetAttribute(gemm_kv_kernel, cudaFuncAttributeMaxDynamicSharedMemorySize, GI_SMEM);
    cudaFuncSetAttribute(gemm_o_kernel,  cudaFuncAttributeMaxDynamicSharedMemorySize, GI_SMEM);

    absmean_all_kernel<<<dim3(256, 4), 256>>>(wq, wk, wv, wo);
    reduce_kernel<<<4, 256>>>();
    wquant_all_kernel<<<dim3(512, 4), 256>>>(wq, wk, wv, wo);

    act_quant_kernel<<<B_ * N_ + B_ * S_, 256>>>(x, y);

    gemm_q_kernel<<<dim3(8, 128), 256, GI_SMEM>>>();
    gemm_kv_kernel<<<dim3(4, 32, 2), 256, GI_SMEM>>>();

    attn_mma_kernel<<<B_ * HQ * (N_ / 64), 128, ATT_SMEM>>>();

    ln_quant_kernel<<<B_ * N_, 256>>>(gamma, beta);
    gemm_o_kernel<<<dim3(8, 128), 256, GI_SMEM>>>(out);
}

// round 7
// speedup vs baseline: 1.5015x; 1.5015x over previous
#include <cuda_runtime.h>
#include <cuda_bf16.h>
#include <cstdint>

#define B_  16
#define N_  1024
#define S_  256
#define D_  1024
#define HQ  16
#define HKV 8
#define HD  64
#define KVE 512

// ---------------- scratch (device globals; no cudaMalloc allowed) ----------
__device__ __nv_bfloat16 g_xq [(size_t)B_*N_*D_];
__device__ __nv_bfloat16 g_yq [(size_t)B_*S_*D_];
__device__ __nv_bfloat16 g_a2q[(size_t)B_*N_*D_];
__device__ __nv_bfloat16 g_wqt[D_*D_];
__device__ __nv_bfloat16 g_wkt[KVE*D_];
__device__ __nv_bfloat16 g_wvt[KVE*D_];
__device__ __nv_bfloat16 g_wot[D_*D_];
// hi/lo bf16 planes for q/k/v (exact fp32 split)
__device__ __nv_bfloat16 g_qh[(size_t)B_*N_*D_];
__device__ __nv_bfloat16 g_ql[(size_t)B_*N_*D_];
__device__ __nv_bfloat16 g_kh[(size_t)B_*S_*KVE];
__device__ __nv_bfloat16 g_kl[(size_t)B_*S_*KVE];
__device__ __nv_bfloat16 g_vh[(size_t)B_*S_*KVE];
__device__ __nv_bfloat16 g_vl[(size_t)B_*S_*KVE];
__device__ float  g_att[(size_t)B_*N_*D_];
__device__ float  g_rfx[B_*N_];
__device__ float  g_rfy[B_*S_];
__device__ float  g_rf2[B_*N_];
__device__ double g_part[4*256];
__device__ double g_wsum[4];

// ---------------- fused block reductions (256 threads) ----------------------
__device__ __forceinline__ float block_sum(float v, float* sbuf) {
    #pragma unroll
    for (int o = 16; o; o >>= 1) v += __shfl_xor_sync(0xffffffffu, v, o);
    int w = threadIdx.x >> 5, l = threadIdx.x & 31;
    if (!l) sbuf[w] = v;
    __syncthreads();
    if (threadIdx.x < 8) {
        v = sbuf[threadIdx.x];
        #pragma unroll
        for (int o = 4; o; o >>= 1) v += __shfl_xor_sync(0x000000ffu, v, o);
        if (!threadIdx.x) sbuf[0] = v;
    }
    __syncthreads();
    v = sbuf[0];
    __syncthreads();
    return v;
}
__device__ __forceinline__ void block_summax(float& s, float& m, float* sbuf) {
    #pragma unroll
    for (int o = 16; o; o >>= 1) {
        s += __shfl_xor_sync(0xffffffffu, s, o);
        m = fmaxf(m, __shfl_xor_sync(0xffffffffu, m, o));
    }
    int w = threadIdx.x >> 5, l = threadIdx.x & 31;
    if (!l) { sbuf[w] = s; sbuf[8 + w] = m; }
    __syncthreads();
    if (threadIdx.x < 8) {
        s = sbuf[threadIdx.x];
        m = sbuf[8 + threadIdx.x];
        #pragma unroll
        for (int o = 4; o; o >>= 1) {
            s += __shfl_xor_sync(0x000000ffu, s, o);
            m = fmaxf(m, __shfl_xor_sync(0x000000ffu, m, o));
        }
        if (!threadIdx.x) { sbuf[0] = s; sbuf[8] = m; }
    }
    __syncthreads();
    s = sbuf[0]; m = sbuf[8];
    __syncthreads();
}
__device__ __forceinline__ void block_sum2(float& a, float& b, float* sbuf) {
    #pragma unroll
    for (int o = 16; o; o >>= 1) {
        a += __shfl_xor_sync(0xffffffffu, a, o);
        b += __shfl_xor_sync(0xffffffffu, b, o);
    }
    int w = threadIdx.x >> 5, l = threadIdx.x & 31;
    if (!l) { sbuf[w] = a; sbuf[8 + w] = b; }
    __syncthreads();
    if (threadIdx.x < 8) {
        a = sbuf[threadIdx.x];
        b = sbuf[8 + threadIdx.x];
        #pragma unroll
        for (int o = 4; o; o >>= 1) {
            a += __shfl_xor_sync(0x000000ffu, a, o);
            b += __shfl_xor_sync(0x000000ffu, b, o);
        }
        if (!threadIdx.x) { sbuf[0] = a; sbuf[8] = b; }
    }
    __syncthreads();
    a = sbuf[0]; b = sbuf[8];
    __syncthreads();
}

// ---------------- weight prep (fused) ----------------------------------------
__global__ void __launch_bounds__(256) absmean_all_kernel(const float* __restrict__ w0,
    const float* __restrict__ w1, const float* __restrict__ w2, const float* __restrict__ w3) {
    __shared__ float sbuf[16];
    int slot = blockIdx.y;
    const float* w = slot == 0 ? w0 : slot == 1 ? w1 : slot == 2 ? w2 : w3;
    int n = (slot == 1 || slot == 2) ? KVE * D_ : D_ * D_;
    float s = 0.f;
    for (int i = blockIdx.x * 256 + threadIdx.x; i < n; i += 256 * 256)
        s += fabsf(w[i]);
    s = block_sum(s, sbuf);
    if (!threadIdx.x) g_part[slot * 256 + blockIdx.x] = (double)s;
}
__global__ void __launch_bounds__(256) reduce_kernel() {
    __shared__ double sd[256];
    int slot = blockIdx.x;
    sd[threadIdx.x] = g_part[slot * 256 + threadIdx.x];
    __syncthreads();
    for (int o = 128; o; o >>= 1) {
        if (threadIdx.x < o) sd[threadIdx.x] += sd[threadIdx.x + o];
        __syncthreads();
    }
    if (!threadIdx.x) g_wsum[slot] = sd[0];
}
__global__ void __launch_bounds__(256) wquant_all_kernel(const float* __restrict__ w0,
    const float* __restrict__ w1, const float* __restrict__ w2, const float* __restrict__ w3) {
    int slot = blockIdx.y;
    const float* w = slot == 0 ? w0 : slot == 1 ? w1 : slot == 2 ? w2 : w3;
    __nv_bfloat16* out = slot == 0 ? g_wqt : slot == 1 ? g_wkt : slot == 2 ? g_wvt : g_wot;
    int n = (slot == 1 || slot == 2) ? KVE * D_ : D_ * D_;
    double invcnt = 1.0 / (double)n;
    float mean  = (float)(g_wsum[slot] * invcnt);
    float scale = 1.0f / fmaxf(mean, 1e-5f);
    for (int i = blockIdx.x * 256 + threadIdx.x; i < n; i += gridDim.x * 256) {
        float t = fminf(fmaxf(rintf(w[i] * scale), -1.f), 1.f);
        out[i] = __float2bfloat16(t);
    }
}

// ---------------- activation quant (x and y fused, bf16 int out) ------------
__global__ void __launch_bounds__(256) act_quant_kernel(const float* __restrict__ X,
                                                        const float* __restrict__ Y) {
    __shared__ float sbuf[16];
    int which = blockIdx.x >= B_ * N_;
    size_t row = which ? blockIdx.x - B_ * N_ : blockIdx.x;
    const float* src = which ? Y : X;
    __nv_bfloat16* Q  = which ? g_yq : g_xq;
    float*         RF = which ? g_rfy : g_rfx;
    int t = threadIdx.x;
    float4 xv = ((const float4*)(src + row * D_))[t];

    float ssq = xv.x*xv.x + xv.y*xv.y + xv.z*xv.z + xv.w*xv.w;
    float am  = fmaxf(fmaxf(fabsf(xv.x), fabsf(xv.y)), fmaxf(fabsf(xv.z), fabsf(xv.w)));
    block_summax(ssq, am, sbuf);
    float r = 1.0f / sqrtf(ssq * (1.0f/1024.0f) + 1e-6f);
    am *= r;
    float sc = 127.0f / fmaxf(am, 1e-5f);

    __nv_bfloat16* qr = Q + row * D_ + t * 4;
    qr[0] = __float2bfloat16(fminf(fmaxf(rintf((xv.x*r)*sc), -128.f), 127.f));
    qr[1] = __float2bfloat16(fminf(fmaxf(rintf((xv.y*r)*sc), -128.f), 127.f));
    qr[2] = __float2bfloat16(fminf(fmaxf(rintf((xv.z*r)*sc), -128.f), 127.f));
    qr[3] = __float2bfloat16(fminf(fmaxf(rintf((xv.w*r)*sc), -128.f), 127.f));
    if (!t) RF[row] = 1.0f / sc;
}

// ---------------- fused LayerNorm + rms_norm + act_quant -------------------
__global__ void __launch_bounds__(256) ln_quant_kernel(const float* __restrict__ gamma,
                                                       const float* __restrict__ beta) {
    __shared__ float sbuf[16];
    size_t row = blockIdx.x;
    int t = threadIdx.x;
    float4 xv = ((const float4*)(g_att + row * D_))[t];

    float s  = xv.x + xv.y + xv.z + xv.w;
    float sq = xv.x*xv.x + xv.y*xv.y + xv.z*xv.z + xv.w*xv.w;
    block_sum2(s, sq, sbuf);
    float mu  = s * (1.0f/1024.0f);
    float var = sq * (1.0f/1024.0f) - mu * mu;
    float rs  = 1.0f / sqrtf(var + 1e-5f);

    float4 gv = ((const float4*)gamma)[t];
    float4 bv = ((const float4*)beta)[t];
    float y0 = ((xv.x-mu)*rs)*gv.x + bv.x, y1 = ((xv.y-mu)*rs)*gv.y + bv.y;
    float y2 = ((xv.z-mu)*rs)*gv.z + bv.z, y3 = ((xv.w-mu)*rs)*gv.w + bv.w;

    float m2 = y0*y0 + y1*y1 + y2*y2 + y3*y3;
    float am = fmaxf(fmaxf(fabsf(y0), fabsf(y1)), fmaxf(fabsf(y2), fabsf(y3)));
    block_summax(m2, am, sbuf);
    float r2 = 1.0f / sqrtf(m2 * (1.0f/1024.0f) + 1e-6f);
    am *= r2;
    float sc = 127.0f / fmaxf(am, 1e-5f);

    __nv_bfloat16* qr = g_a2q + row * D_ + t * 4;
    qr[0] = __float2bfloat16(fminf(fmaxf(rintf((y0*r2)*sc), -128.f), 127.f));
    qr[1] = __float2bfloat16(fminf(fmaxf(rintf((y1*r2)*sc), -128.f), 127.f));
    qr[2] = __float2bfloat16(fminf(fmaxf(rintf((y2*r2)*sc), -128.f), 127.f));
    qr[3] = __float2bfloat16(fminf(fmaxf(rintf((y3*r2)*sc), -128.f), 127.f));
    if (!t) g_rf2[row] = 1.0f / sc;
}

// ---------------- mma / ldmatrix / cp.async helpers -------------------------
__device__ __forceinline__ void ldsm4(uint32_t (&r)[4], uint32_t a) {
    asm volatile("ldmatrix.sync.aligned.m8n8.x4.shared.b16 {%0,%1,%2,%3}, [%4];"
                 : "=r"(r[0]), "=r"(r[1]), "=r"(r[2]), "=r"(r[3]) : "r"(a));
}
__device__ __forceinline__ void ldsm4t(uint32_t (&r)[4], uint32_t a) {
    asm volatile("ldmatrix.sync.aligned.m8n8.x4.trans.shared.b16 {%0,%1,%2,%3}, [%4];"
                 : "=r"(r[0]), "=r"(r[1]), "=r"(r[2]), "=r"(r[3]) : "r"(a));
}
__device__ __forceinline__ void mma_bf16(float (&d)[4], const uint32_t (&a)[4],
                                         uint32_t b0, uint32_t b1) {
    asm volatile("mma.sync.aligned.m16n8k16.row.col.f32.bf16.bf16.f32 "
                 "{%0,%1,%2,%3}, {%4,%5,%6,%7}, {%8,%9}, {%0,%1,%2,%3};"
                 : "+f"(d[0]), "+f"(d[1]), "+f"(d[2]), "+f"(d[3])
                 : "r"(a[0]), "r"(a[1]), "r"(a[2]), "r"(a[3]), "r"(b0), "r"(b1));
}
__device__ __forceinline__ void cpa16(uint32_t s, const void* g) {
    asm volatile("cp.async.cg.shared.global [%0], [%1], 16;" :: "r"(s), "l"(g));
}
#define CP_COMMIT asm volatile("cp.async.commit_group;")
#define CP_WAIT2  asm volatile("cp.async.wait_group 2;")
#define CP_WAIT0  asm volatile("cp.async.wait_group 0;")

__device__ __forceinline__ uint32_t pack_hl(float x, float y, uint32_t& lo) {
    __nv_bfloat16 hx = __float2bfloat16(x), hy = __float2bfloat16(y);
    __nv_bfloat16 lx = __float2bfloat16(x - __bfloat162float(hx));
    __nv_bfloat16 ly = __float2bfloat16(y - __bfloat162float(hy));
    lo = ((uint32_t)__bfloat16_as_ushort(ly) << 16) | __bfloat16_as_ushort(lx);
    return ((uint32_t)__bfloat16_as_ushort(hy) << 16) | __bfloat16_as_ushort(hx);
}

// ---------------- exact integer GEMM via bf16 MMA (4-stage cp.async) -------
#define G_SMEM4 (4 * 10240 * 2)
template<int MODE>   // 0: fp32 C; 1: hi/lo bf16 planes
__device__ __forceinline__ void gemm4(const __nv_bfloat16* __restrict__ A,
                                      const __nv_bfloat16* __restrict__ W,
                                      float* __restrict__ C,
                                      __nv_bfloat16* __restrict__ Ch,
                                      __nv_bfloat16* __restrict__ Cl,
                                      const float* __restrict__ rowf,
                                      int slot, double invcnt, float extra, int Nn) {
    extern __shared__ char smg[];
    __nv_bfloat16* sA = (__nv_bfloat16*)smg;
    __nv_bfloat16* sB = (__nv_bfloat16*)(smg + 4 * 10240);
    const int K = 1024, T = 32;
    int tid = threadIdx.x, lane = tid & 31, w = tid >> 5;
    int warpM = w & 1, warpN = w >> 1;
    int m0 = blockIdx.y * 128, n0 = blockIdx.x * 128;

    float acc[4][4][4];
    #pragma unroll
    for (int a = 0; a < 4; a++)
        #pragma unroll
        for (int b = 0; b < 4; b++)
            #pragma unroll
            for (int c = 0; c < 4; c++) acc[a][b][c] = 0.f;

    uint32_t sAb = (uint32_t)__cvta_generic_to_shared(sA);
    uint32_t sBb = (uint32_t)__cvta_generic_to_shared(sB);
    int aRow = warpM * 64 + (lane & 15);
    int aCol = (lane >> 4) << 3;
    int bRow = warpN * 32 + ((lane & 16) >> 1) + (lane & 7);
    int bCol = lane & 8;
    int ldr = tid >> 2, ldsg = (tid & 3) * 8;

    #define GLOAD(t, buf) do {                                                 \
        uint32_t bo = (uint32_t)(buf) * 10240u;                                \
        int k0 = (t) * 32;                                                     \
        _Pragma("unroll")                                                      \
        for (int i = 0; i < 2; i++) {                                          \
            int r = ldr + i * 64;                                              \
            cpa16(sAb + bo + (uint32_t)((r * 40 + ldsg) * 2),                  \
                  A + (size_t)(m0 + r) * K + k0 + ldsg);                       \
            cpa16(sBb + bo + (uint32_t)((r * 40 + ldsg) * 2),                  \
                  W + (size_t)(n0 + r) * K + k0 + ldsg);                       \
        }                                                                      \
    } while (0)

    GLOAD(0, 0); CP_COMMIT;
    GLOAD(1, 1); CP_COMMIT;
    GLOAD(2, 2); CP_COMMIT;

    #pragma unroll 1
    for (int t = 0; t < T; t++) {
        CP_WAIT2;
        __syncthreads();
        if (t + 3 < T) GLOAD(t + 3, (t + 3) & 3);
        CP_COMMIT;
        uint32_t bo = (uint32_t)(t & 3) * 10240u;
        #pragma unroll
        for (int ks = 0; ks < 32; ks += 16) {
            uint32_t af[4][4];
            #pragma unroll
            for (int mi = 0; mi < 4; mi++)
                ldsm4(af[mi], sAb + bo + (uint32_t)(((aRow + mi * 16) * 40 + ks + aCol) * 2));
            uint32_t bf[2][4];
            #pragma unroll
            for (int nb = 0; nb < 2; nb++)
                ldsm4(bf[nb], sBb + bo + (uint32_t)(((bRow + nb * 16) * 40 + ks + bCol) * 2));
            #pragma unroll
            for (int mi = 0; mi < 4; mi++)
                #pragma unroll
                for (int ni = 0; ni < 4; ni++)
                    mma_bf16(acc[mi][ni], af[mi],
                             bf[ni >> 1][(ni & 1) * 2], bf[ni >> 1][(ni & 1) * 2 + 1]);
        }
        __syncthreads();
    }
    #undef GLOAD

    float wf = fmaxf((float)(g_wsum[slot] * invcnt), 1e-5f);
    float sgl = wf * extra;
    #pragma unroll
    for (int mi = 0; mi < 4; mi++) {
        int m = m0 + warpM * 64 + mi * 16 + (lane >> 2);
        float f0 = rowf[m] * sgl, f1 = rowf[m + 8] * sgl;
        #pragma unroll
        for (int ni = 0; ni < 4; ni++) {
            int n = n0 + warpN * 32 + ni * 8 + (lane & 3) * 2;
            if (MODE == 0) {
                *(float2*)(C + (size_t)m * Nn + n) =
                    make_float2(acc[mi][ni][0] * f0, acc[mi][ni][1] * f0);
                *(float2*)(C + (size_t)(m + 8) * Nn + n) =
                    make_float2(acc[mi][ni][2] * f1, acc[mi][ni][3] * f1);
            } else {
                uint32_t lo0, lo1;
                uint32_t hi0 = pack_hl(acc[mi][ni][0] * f0, acc[mi][ni][1] * f0, lo0);
                uint32_t hi1 = pack_hl(acc[mi][ni][2] * f1, acc[mi][ni][3] * f1, lo1);
                *(uint32_t*)(Ch + (size_t)m * Nn + n) = hi0;
                *(uint32_t*)(Cl + (size_t)m * Nn + n) = lo0;
                *(uint32_t*)(Ch + (size_t)(m + 8) * Nn + n) = hi1;
                *(uint32_t*)(Cl + (size_t)(m + 8) * Nn + n) = lo1;
            }
        }
    }
}

__global__ void __launch_bounds__(256) gemm_q_kernel() {
    gemm4<1>(g_xq, g_wqt, nullptr, g_qh, g_ql, g_rfx, 0, 1.0/(1024.0*1024.0), 0.125f, D_);
}
__global__ void __launch_bounds__(256) gemm_kv_kernel() {
    if (blockIdx.z == 0)
        gemm4<1>(g_yq, g_wkt, nullptr, g_kh, g_kl, g_rfy, 1, 1.0/(512.0*1024.0), 1.0f, KVE);
    else
        gemm4<1>(g_yq, g_wvt, nullptr, g_vh, g_vl, g_rfy, 2, 1.0/(512.0*1024.0), 1.0f, KVE);
}
__global__ void __launch_bounds__(256) gemm_o_kernel(float* __restrict__ out) {
    gemm4<0>(g_a2q, g_wot, out, nullptr, nullptr, g_rf2, 3, 1.0/(1024.0*1024.0), 1.0f, D_);
}

// ---------------- attention: paired GQA heads, hi/lo bf16 MMA ---------------
// Block: 2 q-heads (2h, 2h+1) x 64 q rows; 8 warps (warp>>2 = head group).
// smem bytes: Kh 36864 | Kl 36864 | Vh 36864 | Vl 36864 | Qh0 9216 | Ql0 9216
//             | Qh1 9216 | Ql1 9216   = 184320
#define ATT_SMEM 184320

__global__ void __launch_bounds__(256, 1) attn_mma_kernel() {
    extern __shared__ char smc[];
    uint32_t smb = (uint32_t)__cvta_generic_to_shared(smc);
    const uint32_t oKh = 0, oKl = 36864, oVh = 73728, oVl = 110592, oQ = 147456;

    int tid = threadIdx.x, lane = tid & 31, w = tid >> 5;
    int g = w >> 2, w4 = w & 3;
    int blk = blockIdx.x;
    int qt = blk & 15, h = (blk >> 4) & 7, b = blk >> 7;

    const __nv_bfloat16* Qh0 = g_qh + ((size_t)(b * N_ + qt * 64)) * D_ + (2*h) * HD;
    const __nv_bfloat16* Ql0 = g_ql + ((size_t)(b * N_ + qt * 64)) * D_ + (2*h) * HD;
    const __nv_bfloat16* Kh  = g_kh + (size_t)b * S_ * KVE + h * HD;
    const __nv_bfloat16* Kl  = g_kl + (size_t)b * S_ * KVE + h * HD;
    const __nv_bfloat16* Vh  = g_vh + (size_t)b * S_ * KVE + h * HD;
    const __nv_bfloat16* Vl  = g_vl + (size_t)b * S_ * KVE + h * HD;

    // Q: 2 heads x 64 rows x 8 chunks x 2 planes
    for (int i = tid; i < 512; i += 256) {
        int r = i >> 3, c = (i & 7) * 16;   // c = byte offset in row
        uint32_t so = (uint32_t)(r * 144 + c);
        const size_t go = (size_t)r * D_ + c / 2;
        cpa16(smb + oQ         + so, Qh0 + go);          // head 0 hi
        cpa16(smb + oQ + 9216  + so, Ql0 + go);          // head 0 lo
        cpa16(smb + oQ + 18432 + so, Qh0 + HD + go);     // head 1 hi
        cpa16(smb + oQ + 27648 + so, Ql0 + HD + go);     // head 1 lo
    }
    // K and V: 256 rows x 8 chunks x 2 planes each
    for (int i = tid; i < 2048; i += 256) {
        int r = i >> 3, c = (i & 7) * 16;
        uint32_t so = (uint32_t)(r * 144 + c);
        const size_t go = (size_t)r * KVE + c / 2;
        cpa16(smb + oKh + so, Kh + go);
        cpa16(smb + oKl + so, Kl + go);
        cpa16(smb + oVh + so, Vh + go);
        cpa16(smb + oVl + so, Vl + go);
    }
    CP_COMMIT;
    CP_WAIT0;
    __syncthreads();

    uint32_t sQhB = smb + oQ + (uint32_t)g * 18432u;
    uint32_t sQlB = sQhB + 9216u;
    uint32_t sKhB = smb + oKh, sKlB = smb + oKl;
    uint32_t sVhB = smb + oVh, sVlB = smb + oVl;

    int arow = w4 * 16 + (lane & 15);
    int acb  = (lane & 16) >> 1;
    uint32_t qhf[4][4], qlf[4][4];
    #pragma unroll
    for (int kt = 0; kt < 4; kt++) {
        uint32_t off = (uint32_t)((arow * 72 + kt * 16 + acb) * 2);
        ldsm4(qhf[kt], sQhB + off);
        ldsm4(qlf[kt], sQlB + off);
    }

    float c[32][4];
    #pragma unroll
    for (int i = 0; i < 32; i++)
        #pragma unroll
        for (int j = 0; j < 4; j++) c[i][j] = 0.f;

    int brow = (lane & 7) + ((lane & 16) >> 1);
    int bcol = lane & 8;
    #pragma unroll
    for (int np = 0; np < 16; np++) {
        #pragma unroll
        for (int kt = 0; kt < 4; kt++) {
            uint32_t off = (uint32_t)(((np * 16 + brow) * 72 + kt * 16 + bcol) * 2);
            uint32_t bh[4], bl[4];
            ldsm4(bh, sKhB + off);
            ldsm4(bl, sKlB + off);
            mma_bf16(c[2*np  ], qhf[kt], bh[0], bh[1]);
            mma_bf16(c[2*np  ], qhf[kt], bl[0], bl[1]);
            mma_bf16(c[2*np  ], qlf[kt], bh[0], bh[1]);
            mma_bf16(c[2*np+1], qhf[kt], bh[2], bh[3]);
            mma_bf16(c[2*np+1], qhf[kt], bl[2], bl[3]);
            mma_bf16(c[2*np+1], qlf[kt], bh[2], bh[3]);
        }
    }

    // register softmax (rows lane>>2 and lane>>2 + 8)
    float mx0 = -1e30f, mx1 = -1e30f;
    #pragma unroll
    for (int nt = 0; nt < 32; nt++) {
        mx0 = fmaxf(mx0, fmaxf(c[nt][0], c[nt][1]));
        mx1 = fmaxf(mx1, fmaxf(c[nt][2], c[nt][3]));
    }
    mx0 = fmaxf(mx0, __shfl_xor_sync(0xffffffffu, mx0, 1));
    mx0 = fmaxf(mx0, __shfl_xor_sync(0xffffffffu, mx0, 2));
    mx1 = fmaxf(mx1, __shfl_xor_sync(0xffffffffu, mx1, 1));
    mx1 = fmaxf(mx1, __shfl_xor_sync(0xffffffffu, mx1, 2));
    float s0 = 0.f, s1 = 0.f;
    #pragma unroll
    for (int nt = 0; nt < 32; nt++) {
        c[nt][0] = __expf(c[nt][0] - mx0); s0 += c[nt][0];
        c[nt][1] = __expf(c[nt][1] - mx0); s0 += c[nt][1];
        c[nt][2] = __expf(c[nt][2] - mx1); s1 += c[nt][2];
        c[nt][3] = __expf(c[nt][3] - mx1); s1 += c[nt][3];
    }
    s0 += __shfl_xor_sync(0xffffffffu, s0, 1);
    s0 += __shfl_xor_sync(0xffffffffu, s0, 2);
    s1 += __shfl_xor_sync(0xffffffffu, s1, 1);
    s1 += __shfl_xor_sync(0xffffffffu, s1, 2);
    float i0 = 1.0f / s0, i1 = 1.0f / s1;
    #pragma unroll
    for (int nt = 0; nt < 32; nt++) {
        c[nt][0] *= i0; c[nt][1] *= i0; c[nt][2] *= i1; c[nt][3] *= i1;
    }

    // PV from resident V (no reload, no syncs)
    float o[8][4];
    #pragma unroll
    for (int i = 0; i < 8; i++)
        #pragma unroll
        for (int j = 0; j < 4; j++) o[i][j] = 0.f;

    int vrow = (lane & 7) + (lane & 8);
    int vcb  = (lane & 16) >> 1;
    #pragma unroll
    for (int kt = 0; kt < 16; kt++) {
        uint32_t phi[4], plo[4];
        phi[0] = pack_hl(c[2*kt  ][0], c[2*kt  ][1], plo[0]);
        phi[1] = pack_hl(c[2*kt  ][2], c[2*kt  ][3], plo[1]);
        phi[2] = pack_hl(c[2*kt+1][0], c[2*kt+1][1], plo[2]);
        phi[3] = pack_hl(c[2*kt+1][2], c[2*kt+1][3], plo[3]);
        #pragma unroll
        for (int dp = 0; dp < 4; dp++) {
            uint32_t off = (uint32_t)(((kt * 16 + vrow) * 72 + dp * 16 + vcb) * 2);
            uint32_t bh[4], bl[4];
            ldsm4t(bh, sVhB + off);
            ldsm4t(bl, sVlB + off);
            mma_bf16(o[2*dp  ], phi, bh[0], bh[1]);
            mma_bf16(o[2*dp  ], phi, bl[0], bl[1]);
            mma_bf16(o[2*dp  ], plo, bh[0], bh[1]);
            mma_bf16(o[2*dp+1], phi, bh[2], bh[3]);
            mma_bf16(o[2*dp+1], phi, bl[2], bl[3]);
            mma_bf16(o[2*dp+1], plo, bh[2], bh[3]);
        }
    }

    float* Ob = g_att + ((size_t)(b * N_ + qt * 64 + w4 * 16 + (lane >> 2))) * D_
              + (2 * h + g) * HD;
    #pragma unroll
    for (int nt = 0; nt < 8; nt++) {
        int col = nt * 8 + (lane & 3) * 2;
        *(float2*)(Ob + col)          = make_float2(o[nt][0], o[nt][1]);
        *(float2*)(Ob + 8 * D_ + col) = make_float2(o[nt][2], o[nt][3]);
    }
}

// ---------------- launch ----------------------------------------------------
extern "C" void kernel_launch(void* const* d_in, const int* in_sizes, int n_in,
                              void* d_out, int out_size) {
    const float* x  = (const float*)d_in[0];
    const float* y  = (const float*)d_in[1];
    const float* wq = (const float*)d_in[2];
    const float* wk = (const float*)d_in[3];
    const float* wv = (const float*)d_in[4];
    const float* wo = (const float*)d_in[5];
    const float* gamma = (const float*)d_in[6];
    const float* beta  = (const float*)d_in[7];
    float* out = (float*)d_out;

    cudaFuncSetAttribute(attn_mma_kernel,
                         cudaFuncAttributeMaxDynamicSharedMemorySize, ATT_SMEM);
    cudaFuncSetAttribute(gemm_q_kernel,  cudaFuncAttributeMaxDynamicSharedMemorySize, G_SMEM4);
    cudaFuncSetAttribute(gemm_kv_kernel, cudaFuncAttributeMaxDynamicSharedMemorySize, G_SMEM4);
    cudaFuncSetAttribute(gemm_o_kernel,  cudaFuncAttributeMaxDynamicSharedMemorySize, G_SMEM4);

    absmean_all_kernel<<<dim3(256, 4), 256>>>(wq, wk, wv, wo);
    reduce_kernel<<<4, 256>>>();
    wquant_all_kernel<<<dim3(512, 4), 256>>>(wq, wk, wv, wo);

    act_quant_kernel<<<B_ * N_ + B_ * S_, 256>>>(x, y);

    gemm_q_kernel<<<dim3(8, 128), 256, G_SMEM4>>>();
    gemm_kv_kernel<<<dim3(4, 32, 2), 256, G_SMEM4>>>();

    attn_mma_kernel<<<B_ * HKV * (N_ / 64), 256, ATT_SMEM>>>();

    ln_quant_kernel<<<B_ * N_, 256>>>(gamma, beta);
    gemm_o_kernel<<<dim3(8, 128), 256, G_SMEM4>>>(out);
}

// round 8
// speedup vs baseline: 1.6123x; 1.0738x over previous
#include <cuda_runtime.h>
#include <cuda_bf16.h>
#include <cstdint>

#define B_  16
#define N_  1024
#define S_  256
#define D_  1024
#define HQ  16
#define HKV 8
#define HD  64
#define KVE 512

// ---------------- scratch (device globals; no cudaMalloc allowed) ----------
__device__ __nv_bfloat16 g_xq [(size_t)B_*N_*D_];
__device__ __nv_bfloat16 g_yq [(size_t)B_*S_*D_];
__device__ __nv_bfloat16 g_a2q[(size_t)B_*N_*D_];
__device__ __nv_bfloat16 g_wqt[D_*D_];
__device__ __nv_bfloat16 g_wkt[KVE*D_];
__device__ __nv_bfloat16 g_wvt[KVE*D_];
__device__ __nv_bfloat16 g_wot[D_*D_];
__device__ __nv_bfloat16 g_qh[(size_t)B_*N_*D_];
__device__ __nv_bfloat16 g_ql[(size_t)B_*N_*D_];
__device__ __nv_bfloat16 g_kh[(size_t)B_*S_*KVE];
__device__ __nv_bfloat16 g_kl[(size_t)B_*S_*KVE];
__device__ __nv_bfloat16 g_vh[(size_t)B_*S_*KVE];
__device__ __nv_bfloat16 g_vl[(size_t)B_*S_*KVE];
__device__ float  g_att[(size_t)B_*N_*D_];
__device__ float  g_rfx[B_*N_];
__device__ float  g_rfy[B_*S_];
__device__ float  g_rf2[B_*N_];
__device__ double g_part[4*256];
__device__ double g_wsum[4];

// ---------------- warp reductions -------------------------------------------
__device__ __forceinline__ void warp_sum2(float& a, float& b) {
    #pragma unroll
    for (int o = 16; o; o >>= 1) {
        a += __shfl_xor_sync(0xffffffffu, a, o);
        b += __shfl_xor_sync(0xffffffffu, b, o);
    }
}
__device__ __forceinline__ void warp_summax(float& s, float& m) {
    #pragma unroll
    for (int o = 16; o; o >>= 1) {
        s += __shfl_xor_sync(0xffffffffu, s, o);
        m = fmaxf(m, __shfl_xor_sync(0xffffffffu, m, o));
    }
}
__device__ __forceinline__ float block_sum(float v, float* sbuf) {
    #pragma unroll
    for (int o = 16; o; o >>= 1) v += __shfl_xor_sync(0xffffffffu, v, o);
    int w = threadIdx.x >> 5, l = threadIdx.x & 31;
    if (!l) sbuf[w] = v;
    __syncthreads();
    if (threadIdx.x < 8) {
        v = sbuf[threadIdx.x];
        #pragma unroll
        for (int o = 4; o; o >>= 1) v += __shfl_xor_sync(0x000000ffu, v, o);
        if (!threadIdx.x) sbuf[0] = v;
    }
    __syncthreads();
    v = sbuf[0];
    __syncthreads();
    return v;
}

// ---------------- weight prep (fused) ----------------------------------------
__global__ void __launch_bounds__(256) absmean_all_kernel(const float* __restrict__ w0,
    const float* __restrict__ w1, const float* __restrict__ w2, const float* __restrict__ w3) {
    __shared__ float sbuf[16];
    int slot = blockIdx.y;
    const float* w = slot == 0 ? w0 : slot == 1 ? w1 : slot == 2 ? w2 : w3;
    int n = (slot == 1 || slot == 2) ? KVE * D_ : D_ * D_;
    float s = 0.f;
    for (int i = blockIdx.x * 256 + threadIdx.x; i < n; i += 256 * 256)
        s += fabsf(w[i]);
    s = block_sum(s, sbuf);
    if (!threadIdx.x) g_part[slot * 256 + blockIdx.x] = (double)s;
}
__global__ void __launch_bounds__(256) reduce_kernel() {
    __shared__ double sd[256];
    int slot = blockIdx.x;
    sd[threadIdx.x] = g_part[slot * 256 + threadIdx.x];
    __syncthreads();
    for (int o = 128; o; o >>= 1) {
        if (threadIdx.x < o) sd[threadIdx.x] += sd[threadIdx.x + o];
        __syncthreads();
    }
    if (!threadIdx.x) g_wsum[slot] = sd[0];
}
__global__ void __launch_bounds__(256) wquant_all_kernel(const float* __restrict__ w0,
    const float* __restrict__ w1, const float* __restrict__ w2, const float* __restrict__ w3) {
    int slot = blockIdx.y;
    const float* w = slot == 0 ? w0 : slot == 1 ? w1 : slot == 2 ? w2 : w3;
    __nv_bfloat16* out = slot == 0 ? g_wqt : slot == 1 ? g_wkt : slot == 2 ? g_wvt : g_wot;
    int n = (slot == 1 || slot == 2) ? KVE * D_ : D_ * D_;
    double invcnt = 1.0 / (double)n;
    float mean  = (float)(g_wsum[slot] * invcnt);
    float scale = 1.0f / fmaxf(mean, 1e-5f);
    for (int i = blockIdx.x * 256 + threadIdx.x; i < n; i += gridDim.x * 256) {
        float t = fminf(fmaxf(rintf(w[i] * scale), -1.f), 1.f);
        out[i] = __float2bfloat16(t);
    }
}

// ---------------- activation quant: warp-per-row -----------------------------
__device__ __forceinline__ uint32_t q2(float a, float b, float r, float sc) {
    __nv_bfloat16 qa = __float2bfloat16(fminf(fmaxf(rintf((a*r)*sc), -128.f), 127.f));
    __nv_bfloat16 qb = __float2bfloat16(fminf(fmaxf(rintf((b*r)*sc), -128.f), 127.f));
    return ((uint32_t)__bfloat16_as_ushort(qb) << 16) | __bfloat16_as_ushort(qa);
}

__global__ void __launch_bounds__(256) act_quant_kernel(const float* __restrict__ X,
                                                        const float* __restrict__ Y) {
    int rid  = blockIdx.x * 8 + (threadIdx.x >> 5);
    int lane = threadIdx.x & 31;
    int which = rid >= B_ * N_;
    size_t row = which ? rid - B_ * N_ : rid;
    const float* src = (which ? Y : X) + row * D_;
    __nv_bfloat16* Q  = (which ? g_yq : g_xq) + row * D_;
    float*         RF = which ? g_rfy : g_rfx;

    float4 v[8];
    #pragma unroll
    for (int j = 0; j < 8; j++) v[j] = ((const float4*)src)[lane + j * 32];

    float ssq = 0.f, am = 0.f;
    #pragma unroll
    for (int j = 0; j < 8; j++) {
        ssq += v[j].x*v[j].x + v[j].y*v[j].y + v[j].z*v[j].z + v[j].w*v[j].w;
        am = fmaxf(am, fmaxf(fmaxf(fabsf(v[j].x), fabsf(v[j].y)),
                             fmaxf(fabsf(v[j].z), fabsf(v[j].w))));
    }
    warp_summax(ssq, am);
    float r = 1.0f / sqrtf(ssq * (1.0f/1024.0f) + 1e-6f);
    am *= r;
    float sc = 127.0f / fmaxf(am, 1e-5f);

    #pragma unroll
    for (int j = 0; j < 8; j++) {
        uint2 st;
        st.x = q2(v[j].x, v[j].y, r, sc);
        st.y = q2(v[j].z, v[j].w, r, sc);
        *(uint2*)(Q + (lane + j * 32) * 4) = st;
    }
    if (!lane) RF[row] = 1.0f / sc;
}

// ---------------- fused LayerNorm + rms_norm + act_quant (warp-per-row) ----
__global__ void __launch_bounds__(256) ln_quant_kernel(const float* __restrict__ gamma,
                                                       const float* __restrict__ beta) {
    int rid  = blockIdx.x * 8 + (threadIdx.x >> 5);
    int lane = threadIdx.x & 31;
    const float* src = g_att + (size_t)rid * D_;

    float4 v[8], gv[8], bv[8];
    #pragma unroll
    for (int j = 0; j < 8; j++) {
        v[j]  = ((const float4*)src)[lane + j * 32];
        gv[j] = ((const float4*)gamma)[lane + j * 32];
        bv[j] = ((const float4*)beta)[lane + j * 32];
    }

    float s = 0.f, sq = 0.f;
    #pragma unroll
    for (int j = 0; j < 8; j++) {
        s  += v[j].x + v[j].y + v[j].z + v[j].w;
        sq += v[j].x*v[j].x + v[j].y*v[j].y + v[j].z*v[j].z + v[j].w*v[j].w;
    }
    warp_sum2(s, sq);
    float mu  = s * (1.0f/1024.0f);
    float var = sq * (1.0f/1024.0f) - mu * mu;
    float rs  = 1.0f / sqrtf(var + 1e-5f);

    float m2 = 0.f, am = 0.f;
    #pragma unroll
    for (int j = 0; j < 8; j++) {
        v[j].x = ((v[j].x - mu) * rs) * gv[j].x + bv[j].x;
        v[j].y = ((v[j].y - mu) * rs) * gv[j].y + bv[j].y;
        v[j].z = ((v[j].z - mu) * rs) * gv[j].z + bv[j].z;
        v[j].w = ((v[j].w - mu) * rs) * gv[j].w + bv[j].w;
        m2 += v[j].x*v[j].x + v[j].y*v[j].y + v[j].z*v[j].z + v[j].w*v[j].w;
        am = fmaxf(am, fmaxf(fmaxf(fabsf(v[j].x), fabsf(v[j].y)),
                             fmaxf(fabsf(v[j].z), fabsf(v[j].w))));
    }
    warp_summax(m2, am);
    float r2 = 1.0f / sqrtf(m2 * (1.0f/1024.0f) + 1e-6f);
    am *= r2;
    float sc = 127.0f / fmaxf(am, 1e-5f);

    __nv_bfloat16* Q = g_a2q + (size_t)rid * D_;
    #pragma unroll
    for (int j = 0; j < 8; j++) {
        uint2 st;
        st.x = q2(v[j].x, v[j].y, r2, sc);
        st.y = q2(v[j].z, v[j].w, r2, sc);
        *(uint2*)(Q + (lane + j * 32) * 4) = st;
    }
    if (!lane) g_rf2[rid] = 1.0f / sc;
}

// ---------------- mma / ldmatrix / cp.async helpers -------------------------
__device__ __forceinline__ void ldsm4(uint32_t (&r)[4], uint32_t a) {
    asm volatile("ldmatrix.sync.aligned.m8n8.x4.shared.b16 {%0,%1,%2,%3}, [%4];"
                 : "=r"(r[0]), "=r"(r[1]), "=r"(r[2]), "=r"(r[3]) : "r"(a));
}
__device__ __forceinline__ void ldsm4t(uint32_t (&r)[4], uint32_t a) {
    asm volatile("ldmatrix.sync.aligned.m8n8.x4.trans.shared.b16 {%0,%1,%2,%3}, [%4];"
                 : "=r"(r[0]), "=r"(r[1]), "=r"(r[2]), "=r"(r[3]) : "r"(a));
}
__device__ __forceinline__ void mma_bf16(float (&d)[4], const uint32_t (&a)[4],
                                         uint32_t b0, uint32_t b1) {
    asm volatile("mma.sync.aligned.m16n8k16.row.col.f32.bf16.bf16.f32 "
                 "{%0,%1,%2,%3}, {%4,%5,%6,%7}, {%8,%9}, {%0,%1,%2,%3};"
                 : "+f"(d[0]), "+f"(d[1]), "+f"(d[2]), "+f"(d[3])
                 : "r"(a[0]), "r"(a[1]), "r"(a[2]), "r"(a[3]), "r"(b0), "r"(b1));
}
__device__ __forceinline__ void cpa16(uint32_t s, const void* g) {
    asm volatile("cp.async.cg.shared.global [%0], [%1], 16;" :: "r"(s), "l"(g));
}
#define CP_COMMIT asm volatile("cp.async.commit_group;")
#define CP_WAIT2  asm volatile("cp.async.wait_group 2;")
#define CP_WAIT0  asm volatile("cp.async.wait_group 0;")

__device__ __forceinline__ uint32_t pack_hl(float x, float y, uint32_t& lo) {
    __nv_bfloat16 hx = __float2bfloat16(x), hy = __float2bfloat16(y);
    __nv_bfloat16 lx = __float2bfloat16(x - __bfloat162float(hx));
    __nv_bfloat16 ly = __float2bfloat16(y - __bfloat162float(hy));
    lo = ((uint32_t)__bfloat16_as_ushort(ly) << 16) | __bfloat16_as_ushort(lx);
    return ((uint32_t)__bfloat16_as_ushort(hy) << 16) | __bfloat16_as_ushort(hx);
}

// ---------------- exact integer GEMM via bf16 MMA (4-stage cp.async) -------
#define G_SMEM4 (4 * 10240 * 2)
template<int MODE>   // 0: fp32 C; 1: hi/lo bf16 planes
__device__ __forceinline__ void gemm4(const __nv_bfloat16* __restrict__ A,
                                      const __nv_bfloat16* __restrict__ W,
                                      float* __restrict__ C,
                                      __nv_bfloat16* __restrict__ Ch,
                                      __nv_bfloat16* __restrict__ Cl,
                                      const float* __restrict__ rowf,
                                      int slot, double invcnt, float extra, int Nn) {
    extern __shared__ char smg[];
    __nv_bfloat16* sA = (__nv_bfloat16*)smg;
    __nv_bfloat16* sB = (__nv_bfloat16*)(smg + 4 * 10240);
    const int K = 1024, T = 32;
    int tid = threadIdx.x, lane = tid & 31, w = tid >> 5;
    int warpM = w & 1, warpN = w >> 1;
    int m0 = blockIdx.y * 128, n0 = blockIdx.x * 128;

    float acc[4][4][4];
    #pragma unroll
    for (int a = 0; a < 4; a++)
        #pragma unroll
        for (int b = 0; b < 4; b++)
            #pragma unroll
            for (int c = 0; c < 4; c++) acc[a][b][c] = 0.f;

    uint32_t sAb = (uint32_t)__cvta_generic_to_shared(sA);
    uint32_t sBb = (uint32_t)__cvta_generic_to_shared(sB);
    int aRow = warpM * 64 + (lane & 15);
    int aCol = (lane >> 4) << 3;
    int bRow = warpN * 32 + ((lane & 16) >> 1) + (lane & 7);
    int bCol = lane & 8;
    int ldr = tid >> 2, ldsg = (tid & 3) * 8;

    #define GLOAD(t, buf) do {                                                 \
        uint32_t bo = (uint32_t)(buf) * 10240u;                                \
        int k0 = (t) * 32;                                                     \
        _Pragma("unroll")                                                      \
        for (int i = 0; i < 2; i++) {                                          \
            int r = ldr + i * 64;                                              \
            cpa16(sAb + bo + (uint32_t)((r * 40 + ldsg) * 2),                  \
                  A + (size_t)(m0 + r) * K + k0 + ldsg);                       \
            cpa16(sBb + bo + (uint32_t)((r * 40 + ldsg) * 2),                  \
                  W + (size_t)(n0 + r) * K + k0 + ldsg);                       \
        }                                                                      \
    } while (0)

    GLOAD(0, 0); CP_COMMIT;
    GLOAD(1, 1); CP_COMMIT;
    GLOAD(2, 2); CP_COMMIT;

    #pragma unroll 1
    for (int t = 0; t < T; t++) {
        CP_WAIT2;
        __syncthreads();
        if (t + 3 < T) GLOAD(t + 3, (t + 3) & 3);
        CP_COMMIT;
        uint32_t bo = (uint32_t)(t & 3) * 10240u;
        #pragma unroll
        for (int ks = 0; ks < 32; ks += 16) {
            uint32_t af[4][4];
            #pragma unroll
            for (int mi = 0; mi < 4; mi++)
                ldsm4(af[mi], sAb + bo + (uint32_t)(((aRow + mi * 16) * 40 + ks + aCol) * 2));
            uint32_t bf[2][4];
            #pragma unroll
            for (int nb = 0; nb < 2; nb++)
                ldsm4(bf[nb], sBb + bo + (uint32_t)(((bRow + nb * 16) * 40 + ks + bCol) * 2));
            #pragma unroll
            for (int mi = 0; mi < 4; mi++)
                #pragma unroll
                for (int ni = 0; ni < 4; ni++)
                    mma_bf16(acc[mi][ni], af[mi],
                             bf[ni >> 1][(ni & 1) * 2], bf[ni >> 1][(ni & 1) * 2 + 1]);
        }
        __syncthreads();
    }
    #undef GLOAD

    float wf = fmaxf((float)(g_wsum[slot] * invcnt), 1e-5f);
    float sgl = wf * extra;
    #pragma unroll
    for (int mi = 0; mi < 4; mi++) {
        int m = m0 + warpM * 64 + mi * 16 + (lane >> 2);
        float f0 = rowf[m] * sgl, f1 = rowf[m + 8] * sgl;
        #pragma unroll
        for (int ni = 0; ni < 4; ni++) {
            int n = n0 + warpN * 32 + ni * 8 + (lane & 3) * 2;
            if (MODE == 0) {
                *(float2*)(C + (size_t)m * Nn + n) =
                    make_float2(acc[mi][ni][0] * f0, acc[mi][ni][1] * f0);
                *(float2*)(C + (size_t)(m + 8) * Nn + n) =
                    make_float2(acc[mi][ni][2] * f1, acc[mi][ni][3] * f1);
            } else {
                uint32_t lo0, lo1;
                uint32_t hi0 = pack_hl(acc[mi][ni][0] * f0, acc[mi][ni][1] * f0, lo0);
                uint32_t hi1 = pack_hl(acc[mi][ni][2] * f1, acc[mi][ni][3] * f1, lo1);
                *(uint32_t*)(Ch + (size_t)m * Nn + n) = hi0;
                *(uint32_t*)(Cl + (size_t)m * Nn + n) = lo0;
                *(uint32_t*)(Ch + (size_t)(m + 8) * Nn + n) = hi1;
                *(uint32_t*)(Cl + (size_t)(m + 8) * Nn + n) = lo1;
            }
        }
    }
}

__global__ void __launch_bounds__(256, 2) gemm_q_kernel() {
    gemm4<1>(g_xq, g_wqt, nullptr, g_qh, g_ql, g_rfx, 0, 1.0/(1024.0*1024.0), 0.125f, D_);
}
__global__ void __launch_bounds__(256, 2) gemm_kv_kernel() {
    if (blockIdx.z == 0)
        gemm4<1>(g_yq, g_wkt, nullptr, g_kh, g_kl, g_rfy, 1, 1.0/(512.0*1024.0), 1.0f, KVE);
    else
        gemm4<1>(g_yq, g_wvt, nullptr, g_vh, g_vl, g_rfy, 2, 1.0/(512.0*1024.0), 1.0f, KVE);
}
__global__ void __launch_bounds__(256, 2) gemm_o_kernel(float* __restrict__ out) {
    gemm4<0>(g_a2q, g_wot, out, nullptr, nullptr, g_rf2, 3, 1.0/(1024.0*1024.0), 1.0f, D_);
}

// ---------------- attention: hi/lo-split bf16 MMA (R5 config) --------------
#define ATT_SMEM ((2 * 256 * 72 + 2 * 64 * 72) * 2)

__global__ void __launch_bounds__(128) attn_mma_kernel() {
    extern __shared__ __nv_bfloat16 sm[];
    __nv_bfloat16* sKVh = sm;
    __nv_bfloat16* sKVl = sm + 256 * 72;
    __nv_bfloat16* sQh  = sm + 2 * 256 * 72;
    __nv_bfloat16* sQl  = sQh + 64 * 72;

    int tid = threadIdx.x, lane = tid & 31, w = tid >> 5;
    int blk = blockIdx.x;
    int qt = blk & 15, qh = (blk >> 4) & 15, b = blk >> 8;
    int h = qh >> 1;

    uint32_t sQhB  = (uint32_t)__cvta_generic_to_shared(sQh);
    uint32_t sQlB  = (uint32_t)__cvta_generic_to_shared(sQl);
    uint32_t sKVhB = (uint32_t)__cvta_generic_to_shared(sKVh);
    uint32_t sKVlB = (uint32_t)__cvta_generic_to_shared(sKVl);

    const __nv_bfloat16* Qh = g_qh + ((size_t)(b * N_ + qt * 64)) * D_ + qh * HD;
    const __nv_bfloat16* Ql = g_ql + ((size_t)(b * N_ + qt * 64)) * D_ + qh * HD;
    const __nv_bfloat16* Kh = g_kh + (size_t)b * S_ * KVE + h * HD;
    const __nv_bfloat16* Kl = g_kl + (size_t)b * S_ * KVE + h * HD;
    const __nv_bfloat16* Vh = g_vh + (size_t)b * S_ * KVE + h * HD;
    const __nv_bfloat16* Vl = g_vl + (size_t)b * S_ * KVE + h * HD;

    #pragma unroll
    for (int i = tid; i < 512; i += 128) {
        int r = i >> 3, c = (i & 7) * 16;
        cpa16(sQhB + (uint32_t)(r * 144 + c), Qh + (size_t)r * D_ + c / 2);
        cpa16(sQlB + (uint32_t)(r * 144 + c), Ql + (size_t)r * D_ + c / 2);
    }
    #pragma unroll
    for (int i = tid; i < 2048; i += 128) {
        int r = i >> 3, c = (i & 7) * 16;
        cpa16(sKVhB + (uint32_t)(r * 144 + c), Kh + (size_t)r * KVE + c / 2);
        cpa16(sKVlB + (uint32_t)(r * 144 + c), Kl + (size_t)r * KVE + c / 2);
    }
    CP_COMMIT;
    CP_WAIT0;
    __syncthreads();

    int arow = w * 16 + (lane & 15);
    int acb  = (lane & 16) >> 1;
    uint32_t qhf[4][4], qlf[4][4];
    #pragma unroll
    for (int kt = 0; kt < 4; kt++) {
        uint32_t off = (uint32_t)((arow * 72 + kt * 16 + acb) * 2);
        ldsm4(qhf[kt], sQhB + off);
        ldsm4(qlf[kt], sQlB + off);
    }

    float c[32][4];
    #pragma unroll
    for (int i = 0; i < 32; i++)
        #pragma unroll
        for (int j = 0; j < 4; j++) c[i][j] = 0.f;

    int brow = (lane & 7) + ((lane & 16) >> 1);
    int bcol = lane & 8;
    #pragma unroll
    for (int np = 0; np < 16; np++) {
        #pragma unroll
        for (int kt = 0; kt < 4; kt++) {
            uint32_t off = (uint32_t)(((np * 16 + brow) * 72 + kt * 16 + bcol) * 2);
            uint32_t bh[4], bl[4];
            ldsm4(bh, sKVhB + off);
            ldsm4(bl, sKVlB + off);
            mma_bf16(c[2*np  ], qhf[kt], bh[0], bh[1]);
            mma_bf16(c[2*np  ], qhf[kt], bl[0], bl[1]);
            mma_bf16(c[2*np  ], qlf[kt], bh[0], bh[1]);
            mma_bf16(c[2*np+1], qhf[kt], bh[2], bh[3]);
            mma_bf16(c[2*np+1], qhf[kt], bl[2], bl[3]);
            mma_bf16(c[2*np+1], qlf[kt], bh[2], bh[3]);
        }
    }
    __syncthreads();

    #pragma unroll
    for (int i = tid; i < 2048; i += 128) {
        int r = i >> 3, cc = (i & 7) * 16;
        cpa16(sKVhB + (uint32_t)(r * 144 + cc), Vh + (size_t)r * KVE + cc / 2);
        cpa16(sKVlB + (uint32_t)(r * 144 + cc), Vl + (size_t)r * KVE + cc / 2);
    }
    CP_COMMIT;

    float mx0 = -1e30f, mx1 = -1e30f;
    #pragma unroll
    for (int nt = 0; nt < 32; nt++) {
        mx0 = fmaxf(mx0, fmaxf(c[nt][0], c[nt][1]));
        mx1 = fmaxf(mx1, fmaxf(c[nt][2], c[nt][3]));
    }
    mx0 = fmaxf(mx0, __shfl_xor_sync(0xffffffffu, mx0, 1));
    mx0 = fmaxf(mx0, __shfl_xor_sync(0xffffffffu, mx0, 2));
    mx1 = fmaxf(mx1, __shfl_xor_sync(0xffffffffu, mx1, 1));
    mx1 = fmaxf(mx1, __shfl_xor_sync(0xffffffffu, mx1, 2));
    float s0 = 0.f, s1 = 0.f;
    #pragma unroll
    for (int nt = 0; nt < 32; nt++) {
        c[nt][0] = __expf(c[nt][0] - mx0); s0 += c[nt][0];
        c[nt][1] = __expf(c[nt][1] - mx0); s0 += c[nt][1];
        c[nt][2] = __expf(c[nt][2] - mx1); s1 += c[nt][2];
        c[nt][3] = __expf(c[nt][3] - mx1); s1 += c[nt][3];
    }
    s0 += __shfl_xor_sync(0xffffffffu, s0, 1);
    s0 += __shfl_xor_sync(0xffffffffu, s0, 2);
    s1 += __shfl_xor_sync(0xffffffffu, s1, 1);
    s1 += __shfl_xor_sync(0xffffffffu, s1, 2);
    float i0 = 1.0f / s0, i1 = 1.0f / s1;
    #pragma unroll
    for (int nt = 0; nt < 32; nt++) {
        c[nt][0] *= i0; c[nt][1] *= i0; c[nt][2] *= i1; c[nt][3] *= i1;
    }
    CP_WAIT0;
    __syncthreads();

    float o[8][4];
    #pragma unroll
    for (int i = 0; i < 8; i++)
        #pragma unroll
        for (int j = 0; j < 4; j++) o[i][j] = 0.f;

    int vrow = (lane & 7) + (lane & 8);
    int vcb  = (lane & 16) >> 1;
    #pragma unroll
    for (int kt = 0; kt < 16; kt++) {
        uint32_t phi[4], plo[4];
        phi[0] = pack_hl(c[2*kt  ][0], c[2*kt  ][1], plo[0]);
        phi[1] = pack_hl(c[2*kt  ][2], c[2*kt  ][3], plo[1]);
        phi[2] = pack_hl(c[2*kt+1][0], c[2*kt+1][1], plo[2]);
        phi[3] = pack_hl(c[2*kt+1][2], c[2*kt+1][3], plo[3]);
        #pragma unroll
        for (int dp = 0; dp < 4; dp++) {
            uint32_t off = (uint32_t)(((kt * 16 + vrow) * 72 + dp * 16 + vcb) * 2);
            uint32_t bh[4], bl[4];
            ldsm4t(bh, sKVhB + off);
            ldsm4t(bl, sKVlB + off);
            mma_bf16(o[2*dp  ], phi, bh[0], bh[1]);
            mma_bf16(o[2*dp  ], phi, bl[0], bl[1]);
            mma_bf16(o[2*dp  ], plo, bh[0], bh[1]);
            mma_bf16(o[2*dp+1], phi, bh[2], bh[3]);
            mma_bf16(o[2*dp+1], phi, bl[2], bl[3]);
            mma_bf16(o[2*dp+1], plo, bh[2], bh[3]);
        }
    }

    float* Ob = g_att + ((size_t)(b * N_ + qt * 64 + w * 16 + (lane >> 2))) * D_ + qh * HD;
    #pragma unroll
    for (int nt = 0; nt < 8; nt++) {
        int col = nt * 8 + (lane & 3) * 2;
        *(float2*)(Ob + col)          = make_float2(o[nt][0], o[nt][1]);
        *(float2*)(Ob + 8 * D_ + col) = make_float2(o[nt][2], o[nt][3]);
    }
}

// ---------------- launch ----------------------------------------------------
extern "C" void kernel_launch(void* const* d_in, const int* in_sizes, int n_in,
                              void* d_out, int out_size) {
    const float* x  = (const float*)d_in[0];
    const float* y  = (const float*)d_in[1];
    const float* wq = (const float*)d_in[2];
    const float* wk = (const float*)d_in[3];
    const float* wv = (const float*)d_in[4];
    const float* wo = (const float*)d_in[5];
    const float* gamma = (const float*)d_in[6];
    const float* beta  = (const float*)d_in[7];
    float* out = (float*)d_out;

    cudaFuncSetAttribute(attn_mma_kernel,
                         cudaFuncAttributeMaxDynamicSharedMemorySize, ATT_SMEM);
    cudaFuncSetAttribute(gemm_q_kernel,  cudaFuncAttributeMaxDynamicSharedMemorySize, G_SMEM4);
    cudaFuncSetAttribute(gemm_kv_kernel, cudaFuncAttributeMaxDynamicSharedMemorySize, G_SMEM4);
    cudaFuncSetAttribute(gemm_o_kernel,  cudaFuncAttributeMaxDynamicSharedMemorySize, G_SMEM4);

    absmean_all_kernel<<<dim3(256, 4), 256>>>(wq, wk, wv, wo);
    reduce_kernel<<<4, 256>>>();
    wquant_all_kernel<<<dim3(512, 4), 256>>>(wq, wk, wv, wo);

    act_quant_kernel<<<(B_ * N_ + B_ * S_) / 8, 256>>>(x, y);

    gemm_q_kernel<<<dim3(8, 128), 256, G_SMEM4>>>();
    gemm_kv_kernel<<<dim3(4, 32, 2), 256, G_SMEM4>>>();

    attn_mma_kernel<<<B_ * HQ * (N_ / 64), 128, ATT_SMEM>>>();

    ln_quant_kernel<<<B_ * N_ / 8, 256>>>(gamma, beta);
    gemm_o_kernel<<<dim3(8, 128), 256, G_SMEM4>>>(out);
}

// round 9
// speedup vs baseline: 1.6374x; 1.0156x over previous
#include <cuda_runtime.h>
#include <cuda_bf16.h>
#include <cstdint>

#define B_  16
#define N_  1024
#define S_  256
#define D_  1024
#define HQ  16
#define HKV 8
#define HD  64
#define KVE 512

// ---------------- scratch (device globals; no cudaMalloc allowed) ----------
__device__ __nv_bfloat16 g_xq [(size_t)B_*N_*D_];
__device__ __nv_bfloat16 g_yq [(size_t)B_*S_*D_];
__device__ __nv_bfloat16 g_a2q[(size_t)B_*N_*D_];
__device__ __nv_bfloat16 g_wqt[D_*D_];
__device__ __nv_bfloat16 g_wkt[KVE*D_];
__device__ __nv_bfloat16 g_wvt[KVE*D_];
__device__ __nv_bfloat16 g_wot[D_*D_];
__device__ __nv_bfloat16 g_qh[(size_t)B_*N_*D_];
__device__ __nv_bfloat16 g_ql[(size_t)B_*N_*D_];
__device__ __nv_bfloat16 g_kh[(size_t)B_*S_*KVE];
__device__ __nv_bfloat16 g_kl[(size_t)B_*S_*KVE];
__device__ __nv_bfloat16 g_vh[(size_t)B_*S_*KVE];
__device__ __nv_bfloat16 g_vl[(size_t)B_*S_*KVE];
__device__ float  g_att[(size_t)B_*N_*D_];
__device__ float  g_rfx[B_*N_];
__device__ float  g_rfy[B_*S_];
__device__ float  g_rf2[B_*N_];
__device__ double g_part[4*256];
__device__ double g_wsum[4];

// ---------------- warp reductions -------------------------------------------
__device__ __forceinline__ void warp_sum2(float& a, float& b) {
    #pragma unroll
    for (int o = 16; o; o >>= 1) {
        a += __shfl_xor_sync(0xffffffffu, a, o);
        b += __shfl_xor_sync(0xffffffffu, b, o);
    }
}
__device__ __forceinline__ void warp_summax(float& s, float& m) {
    #pragma unroll
    for (int o = 16; o; o >>= 1) {
        s += __shfl_xor_sync(0xffffffffu, s, o);
        m = fmaxf(m, __shfl_xor_sync(0xffffffffu, m, o));
    }
}
__device__ __forceinline__ float block_sum(float v, float* sbuf) {
    #pragma unroll
    for (int o = 16; o; o >>= 1) v += __shfl_xor_sync(0xffffffffu, v, o);
    int w = threadIdx.x >> 5, l = threadIdx.x & 31;
    if (!l) sbuf[w] = v;
    __syncthreads();
    if (threadIdx.x < 8) {
        v = sbuf[threadIdx.x];
        #pragma unroll
        for (int o = 4; o; o >>= 1) v += __shfl_xor_sync(0x000000ffu, v, o);
        if (!threadIdx.x) sbuf[0] = v;
    }
    __syncthreads();
    v = sbuf[0];
    __syncthreads();
    return v;
}

// ---------------- weight prep (fused) ----------------------------------------
__global__ void __launch_bounds__(256) absmean_all_kernel(const float* __restrict__ w0,
    const float* __restrict__ w1, const float* __restrict__ w2, const float* __restrict__ w3) {
    __shared__ float sbuf[16];
    int slot = blockIdx.y;
    const float* w = slot == 0 ? w0 : slot == 1 ? w1 : slot == 2 ? w2 : w3;
    int n = (slot == 1 || slot == 2) ? KVE * D_ : D_ * D_;
    float s = 0.f;
    for (int i = blockIdx.x * 256 + threadIdx.x; i < n; i += 256 * 256)
        s += fabsf(w[i]);
    s = block_sum(s, sbuf);
    if (!threadIdx.x) g_part[slot * 256 + blockIdx.x] = (double)s;
}
__global__ void __launch_bounds__(256) reduce_kernel() {
    __shared__ double sd[256];
    int slot = blockIdx.x;
    sd[threadIdx.x] = g_part[slot * 256 + threadIdx.x];
    __syncthreads();
    for (int o = 128; o; o >>= 1) {
        if (threadIdx.x < o) sd[threadIdx.x] += sd[threadIdx.x + o];
        __syncthreads();
    }
    if (!threadIdx.x) g_wsum[slot] = sd[0];
}
__global__ void __launch_bounds__(256) wquant_all_kernel(const float* __restrict__ w0,
    const float* __restrict__ w1, const float* __restrict__ w2, const float* __restrict__ w3) {
    int slot = blockIdx.y;
    const float* w = slot == 0 ? w0 : slot == 1 ? w1 : slot == 2 ? w2 : w3;
    __nv_bfloat16* out = slot == 0 ? g_wqt : slot == 1 ? g_wkt : slot == 2 ? g_wvt : g_wot;
    int n = (slot == 1 || slot == 2) ? KVE * D_ : D_ * D_;
    double invcnt = 1.0 / (double)n;
    float mean  = (float)(g_wsum[slot] * invcnt);
    float scale = 1.0f / fmaxf(mean, 1e-5f);
    for (int i = blockIdx.x * 256 + threadIdx.x; i < n; i += gridDim.x * 256) {
        float t = fminf(fmaxf(rintf(w[i] * scale), -1.f), 1.f);
        out[i] = __float2bfloat16(t);
    }
}

// ---------------- activation quant: warp-per-row -----------------------------
__device__ __forceinline__ uint32_t q2(float a, float b, float r, float sc) {
    __nv_bfloat16 qa = __float2bfloat16(fminf(fmaxf(rintf((a*r)*sc), -128.f), 127.f));
    __nv_bfloat16 qb = __float2bfloat16(fminf(fmaxf(rintf((b*r)*sc), -128.f), 127.f));
    return ((uint32_t)__bfloat16_as_ushort(qb) << 16) | __bfloat16_as_ushort(qa);
}

__global__ void __launch_bounds__(256) act_quant_kernel(const float* __restrict__ X,
                                                        const float* __restrict__ Y) {
    int rid  = blockIdx.x * 8 + (threadIdx.x >> 5);
    int lane = threadIdx.x & 31;
    int which = rid >= B_ * N_;
    size_t row = which ? rid - B_ * N_ : rid;
    const float* src = (which ? Y : X) + row * D_;
    __nv_bfloat16* Q  = (which ? g_yq : g_xq) + row * D_;
    float*         RF = which ? g_rfy : g_rfx;

    float4 v[8];
    #pragma unroll
    for (int j = 0; j < 8; j++) v[j] = ((const float4*)src)[lane + j * 32];

    float ssq = 0.f, am = 0.f;
    #pragma unroll
    for (int j = 0; j < 8; j++) {
        ssq += v[j].x*v[j].x + v[j].y*v[j].y + v[j].z*v[j].z + v[j].w*v[j].w;
        am = fmaxf(am, fmaxf(fmaxf(fabsf(v[j].x), fabsf(v[j].y)),
                             fmaxf(fabsf(v[j].z), fabsf(v[j].w))));
    }
    warp_summax(ssq, am);
    float r = 1.0f / sqrtf(ssq * (1.0f/1024.0f) + 1e-6f);
    am *= r;
    float sc = 127.0f / fmaxf(am, 1e-5f);

    #pragma unroll
    for (int j = 0; j < 8; j++) {
        uint2 st;
        st.x = q2(v[j].x, v[j].y, r, sc);
        st.y = q2(v[j].z, v[j].w, r, sc);
        *(uint2*)(Q + (lane + j * 32) * 4) = st;
    }
    if (!lane) RF[row] = 1.0f / sc;
}

// ---------------- fused LayerNorm + rms_norm + act_quant (warp-per-row) ----
__global__ void __launch_bounds__(256) ln_quant_kernel(const float* __restrict__ gamma,
                                                       const float* __restrict__ beta) {
    int rid  = blockIdx.x * 8 + (threadIdx.x >> 5);
    int lane = threadIdx.x & 31;
    const float* src = g_att + (size_t)rid * D_;

    float4 v[8], gv[8], bv[8];
    #pragma unroll
    for (int j = 0; j < 8; j++) {
        v[j]  = ((const float4*)src)[lane + j * 32];
        gv[j] = ((const float4*)gamma)[lane + j * 32];
        bv[j] = ((const float4*)beta)[lane + j * 32];
    }

    float s = 0.f, sq = 0.f;
    #pragma unroll
    for (int j = 0; j < 8; j++) {
        s  += v[j].x + v[j].y + v[j].z + v[j].w;
        sq += v[j].x*v[j].x + v[j].y*v[j].y + v[j].z*v[j].z + v[j].w*v[j].w;
    }
    warp_sum2(s, sq);
    float mu  = s * (1.0f/1024.0f);
    float var = sq * (1.0f/1024.0f) - mu * mu;
    float rs  = 1.0f / sqrtf(var + 1e-5f);

    float m2 = 0.f, am = 0.f;
    #pragma unroll
    for (int j = 0; j < 8; j++) {
        v[j].x = ((v[j].x - mu) * rs) * gv[j].x + bv[j].x;
        v[j].y = ((v[j].y - mu) * rs) * gv[j].y + bv[j].y;
        v[j].z = ((v[j].z - mu) * rs) * gv[j].z + bv[j].z;
        v[j].w = ((v[j].w - mu) * rs) * gv[j].w + bv[j].w;
        m2 += v[j].x*v[j].x + v[j].y*v[j].y + v[j].z*v[j].z + v[j].w*v[j].w;
        am = fmaxf(am, fmaxf(fmaxf(fabsf(v[j].x), fabsf(v[j].y)),
                             fmaxf(fabsf(v[j].z), fabsf(v[j].w))));
    }
    warp_summax(m2, am);
    float r2 = 1.0f / sqrtf(m2 * (1.0f/1024.0f) + 1e-6f);
    am *= r2;
    float sc = 127.0f / fmaxf(am, 1e-5f);

    __nv_bfloat16* Q = g_a2q + (size_t)rid * D_;
    #pragma unroll
    for (int j = 0; j < 8; j++) {
        uint2 st;
        st.x = q2(v[j].x, v[j].y, r2, sc);
        st.y = q2(v[j].z, v[j].w, r2, sc);
        *(uint2*)(Q + (lane + j * 32) * 4) = st;
    }
    if (!lane) g_rf2[rid] = 1.0f / sc;
}

// ---------------- mma / ldmatrix / cp.async helpers -------------------------
__device__ __forceinline__ void ldsm4(uint32_t (&r)[4], uint32_t a) {
    asm volatile("ldmatrix.sync.aligned.m8n8.x4.shared.b16 {%0,%1,%2,%3}, [%4];"
                 : "=r"(r[0]), "=r"(r[1]), "=r"(r[2]), "=r"(r[3]) : "r"(a));
}
__device__ __forceinline__ void ldsm4t(uint32_t (&r)[4], uint32_t a) {
    asm volatile("ldmatrix.sync.aligned.m8n8.x4.trans.shared.b16 {%0,%1,%2,%3}, [%4];"
                 : "=r"(r[0]), "=r"(r[1]), "=r"(r[2]), "=r"(r[3]) : "r"(a));
}
__device__ __forceinline__ void mma_bf16(float (&d)[4], const uint32_t (&a)[4],
                                         uint32_t b0, uint32_t b1) {
    asm volatile("mma.sync.aligned.m16n8k16.row.col.f32.bf16.bf16.f32 "
                 "{%0,%1,%2,%3}, {%4,%5,%6,%7}, {%8,%9}, {%0,%1,%2,%3};"
                 : "+f"(d[0]), "+f"(d[1]), "+f"(d[2]), "+f"(d[3])
                 : "r"(a[0]), "r"(a[1]), "r"(a[2]), "r"(a[3]), "r"(b0), "r"(b1));
}
__device__ __forceinline__ void cpa16(uint32_t s, const void* g) {
    asm volatile("cp.async.cg.shared.global [%0], [%1], 16;" :: "r"(s), "l"(g));
}
#define CP_COMMIT asm volatile("cp.async.commit_group;")
#define CP_WAIT2  asm volatile("cp.async.wait_group 2;")
#define CP_WAIT0  asm volatile("cp.async.wait_group 0;")

__device__ __forceinline__ uint32_t pack_hl(float x, float y, uint32_t& lo) {
    __nv_bfloat16 hx = __float2bfloat16(x), hy = __float2bfloat16(y);
    __nv_bfloat16 lx = __float2bfloat16(x - __bfloat162float(hx));
    __nv_bfloat16 ly = __float2bfloat16(y - __bfloat162float(hy));
    lo = ((uint32_t)__bfloat16_as_ushort(ly) << 16) | __bfloat16_as_ushort(lx);
    return ((uint32_t)__bfloat16_as_ushort(hy) << 16) | __bfloat16_as_ushort(hx);
}

// ---------------- exact integer GEMM via bf16 MMA (4-stage cp.async) -------
#define G_SMEM4 (4 * 10240 * 2)
template<int MODE>   // 0: fp32 C; 1: hi/lo bf16 planes
__device__ __forceinline__ void gemm4(const __nv_bfloat16* __restrict__ A,
                                      const __nv_bfloat16* __restrict__ W,
                                      float* __restrict__ C,
                                      __nv_bfloat16* __restrict__ Ch,
                                      __nv_bfloat16* __restrict__ Cl,
                                      const float* __restrict__ rowf,
                                      int slot, double invcnt, float extra, int Nn,
                                      int m0, int n0) {
    extern __shared__ char smg[];
    __nv_bfloat16* sA = (__nv_bfloat16*)smg;
    __nv_bfloat16* sB = (__nv_bfloat16*)(smg + 4 * 10240);
    const int K = 1024, T = 32;
    int tid = threadIdx.x, lane = tid & 31, w = tid >> 5;
    int warpM = w & 1, warpN = w >> 1;

    float acc[4][4][4];
    #pragma unroll
    for (int a = 0; a < 4; a++)
        #pragma unroll
        for (int b = 0; b < 4; b++)
            #pragma unroll
            for (int c = 0; c < 4; c++) acc[a][b][c] = 0.f;

    uint32_t sAb = (uint32_t)__cvta_generic_to_shared(sA);
    uint32_t sBb = (uint32_t)__cvta_generic_to_shared(sB);
    int aRow = warpM * 64 + (lane & 15);
    int aCol = (lane >> 4) << 3;
    int bRow = warpN * 32 + ((lane & 16) >> 1) + (lane & 7);
    int bCol = lane & 8;
    int ldr = tid >> 2, ldsg = (tid & 3) * 8;

    #define GLOAD(t, buf) do {                                                 \
        uint32_t bo = (uint32_t)(buf) * 10240u;                                \
        int k0 = (t) * 32;                                                     \
        _Pragma("unroll")                                                      \
        for (int i = 0; i < 2; i++) {                                          \
            int r = ldr + i * 64;                                              \
            cpa16(sAb + bo + (uint32_t)((r * 40 + ldsg) * 2),                  \
                  A + (size_t)(m0 + r) * K + k0 + ldsg);                       \
            cpa16(sBb + bo + (uint32_t)((r * 40 + ldsg) * 2),                  \
                  W + (size_t)(n0 + r) * K + k0 + ldsg);                       \
        }                                                                      \
    } while (0)

    GLOAD(0, 0); CP_COMMIT;
    GLOAD(1, 1); CP_COMMIT;
    GLOAD(2, 2); CP_COMMIT;

    #pragma unroll 1
    for (int t = 0; t < T; t++) {
        CP_WAIT2;
        __syncthreads();
        if (t + 3 < T) GLOAD(t + 3, (t + 3) & 3);
        CP_COMMIT;
        uint32_t bo = (uint32_t)(t & 3) * 10240u;
        #pragma unroll
        for (int ks = 0; ks < 32; ks += 16) {
            uint32_t af[4][4];
            #pragma unroll
            for (int mi = 0; mi < 4; mi++)
                ldsm4(af[mi], sAb + bo + (uint32_t)(((aRow + mi * 16) * 40 + ks + aCol) * 2));
            uint32_t bf[2][4];
            #pragma unroll
            for (int nb = 0; nb < 2; nb++)
                ldsm4(bf[nb], sBb + bo + (uint32_t)(((bRow + nb * 16) * 40 + ks + bCol) * 2));
            #pragma unroll
            for (int mi = 0; mi < 4; mi++)
                #pragma unroll
                for (int ni = 0; ni < 4; ni++)
                    mma_bf16(acc[mi][ni], af[mi],
                             bf[ni >> 1][(ni & 1) * 2], bf[ni >> 1][(ni & 1) * 2 + 1]);
        }
        // NOTE: no trailing barrier — next iteration's top barrier (after
        // CP_WAIT2) orders MMA reads of buf t before GLOAD(t+4) overwrites it.
    }
    #undef GLOAD

    float wf = fmaxf((float)(g_wsum[slot] * invcnt), 1e-5f);
    float sgl = wf * extra;
    #pragma unroll
    for (int mi = 0; mi < 4; mi++) {
        int m = m0 + warpM * 64 + mi * 16 + (lane >> 2);
        float f0 = rowf[m] * sgl, f1 = rowf[m + 8] * sgl;
        #pragma unroll
        for (int ni = 0; ni < 4; ni++) {
            int n = n0 + warpN * 32 + ni * 8 + (lane & 3) * 2;
            if (MODE == 0) {
                *(float2*)(C + (size_t)m * Nn + n) =
                    make_float2(acc[mi][ni][0] * f0, acc[mi][ni][1] * f0);
                *(float2*)(C + (size_t)(m + 8) * Nn + n) =
                    make_float2(acc[mi][ni][2] * f1, acc[mi][ni][3] * f1);
            } else {
                uint32_t lo0, lo1;
                uint32_t hi0 = pack_hl(acc[mi][ni][0] * f0, acc[mi][ni][1] * f0, lo0);
                uint32_t hi1 = pack_hl(acc[mi][ni][2] * f1, acc[mi][ni][3] * f1, lo1);
                *(uint32_t*)(Ch + (size_t)m * Nn + n) = hi0;
                *(uint32_t*)(Cl + (size_t)m * Nn + n) = lo0;
                *(uint32_t*)(Ch + (size_t)(m + 8) * Nn + n) = hi1;
                *(uint32_t*)(Cl + (size_t)(m + 8) * Nn + n) = lo1;
            }
        }
    }
}

// merged q/k/v projection GEMM: blocks [0,1024) = q, [1024,1152) = k, [1152,1280) = v
__global__ void __launch_bounds__(256, 2) gemm_qkv_kernel() {
    int blk = blockIdx.x;
    if (blk < 1024) {
        gemm4<1>(g_xq, g_wqt, nullptr, g_qh, g_ql, g_rfx, 0, 1.0/(1024.0*1024.0),
                 0.125f, D_, (blk >> 3) * 128, (blk & 7) * 128);
    } else if (blk < 1152) {
        int t = blk - 1024;
        gemm4<1>(g_yq, g_wkt, nullptr, g_kh, g_kl, g_rfy, 1, 1.0/(512.0*1024.0),
                 1.0f, KVE, (t >> 2) * 128, (t & 3) * 128);
    } else {
        int t = blk - 1152;
        gemm4<1>(g_yq, g_wvt, nullptr, g_vh, g_vl, g_rfy, 2, 1.0/(512.0*1024.0),
                 1.0f, KVE, (t >> 2) * 128, (t & 3) * 128);
    }
}
__global__ void __launch_bounds__(256, 2) gemm_o_kernel(float* __restrict__ out) {
    gemm4<0>(g_a2q, g_wot, out, nullptr, nullptr, g_rf2, 3, 1.0/(1024.0*1024.0),
             1.0f, D_, (int)blockIdx.y * 128, (int)blockIdx.x * 128);
}

// ---------------- attention: hi/lo-split bf16 MMA ---------------------------
#define ATT_SMEM ((2 * 256 * 72 + 2 * 64 * 72) * 2)

__global__ void __launch_bounds__(128) attn_mma_kernel() {
    extern __shared__ __nv_bfloat16 sm[];
    __nv_bfloat16* sKVh = sm;
    __nv_bfloat16* sKVl = sm + 256 * 72;
    __nv_bfloat16* sQh  = sm + 2 * 256 * 72;
    __nv_bfloat16* sQl  = sQh + 64 * 72;

    int tid = threadIdx.x, lane = tid & 31, w = tid >> 5;
    int blk = blockIdx.x;
    int qt = blk & 15, qh = (blk >> 4) & 15, b = blk >> 8;
    int h = qh >> 1;

    uint32_t sQhB  = (uint32_t)__cvta_generic_to_shared(sQh);
    uint32_t sQlB  = (uint32_t)__cvta_generic_to_shared(sQl);
    uint32_t sKVhB = (uint32_t)__cvta_generic_to_shared(sKVh);
    uint32_t sKVlB = (uint32_t)__cvta_generic_to_shared(sKVl);

    const __nv_bfloat16* Qh = g_qh + ((size_t)(b * N_ + qt * 64)) * D_ + qh * HD;
    const __nv_bfloat16* Ql = g_ql + ((size_t)(b * N_ + qt * 64)) * D_ + qh * HD;
    const __nv_bfloat16* Kh = g_kh + (size_t)b * S_ * KVE + h * HD;
    const __nv_bfloat16* Kl = g_kl + (size_t)b * S_ * KVE + h * HD;
    const __nv_bfloat16* Vh = g_vh + (size_t)b * S_ * KVE + h * HD;
    const __nv_bfloat16* Vl = g_vl + (size_t)b * S_ * KVE + h * HD;

    #pragma unroll
    for (int i = tid; i < 512; i += 128) {
        int r = i >> 3, c = (i & 7) * 16;
        cpa16(sQhB + (uint32_t)(r * 144 + c), Qh + (size_t)r * D_ + c / 2);
        cpa16(sQlB + (uint32_t)(r * 144 + c), Ql + (size_t)r * D_ + c / 2);
    }
    #pragma unroll
    for (int i = tid; i < 2048; i += 128) {
        int r = i >> 3, c = (i & 7) * 16;
        cpa16(sKVhB + (uint32_t)(r * 144 + c), Kh + (size_t)r * KVE + c / 2);
        cpa16(sKVlB + (uint32_t)(r * 144 + c), Kl + (size_t)r * KVE + c / 2);
    }
    CP_COMMIT;
    CP_WAIT0;
    __syncthreads();

    int arow = w * 16 + (lane & 15);
    int acb  = (lane & 16) >> 1;
    uint32_t qhf[4][4], qlf[4][4];
    #pragma unroll
    for (int kt = 0; kt < 4; kt++) {
        uint32_t off = (uint32_t)((arow * 72 + kt * 16 + acb) * 2);
        ldsm4(qhf[kt], sQhB + off);
        ldsm4(qlf[kt], sQlB + off);
    }

    float c[32][4];
    #pragma unroll
    for (int i = 0; i < 32; i++)
        #pragma unroll
        for (int j = 0; j < 4; j++) c[i][j] = 0.f;

    int brow = (lane & 7) + ((lane & 16) >> 1);
    int bcol = lane & 8;
    #pragma unroll
    for (int np = 0; np < 16; np++) {
        #pragma unroll
        for (int kt = 0; kt < 4; kt++) {
            uint32_t off = (uint32_t)(((np * 16 + brow) * 72 + kt * 16 + bcol) * 2);
            uint32_t bh[4], bl[4];
            ldsm4(bh, sKVhB + off);
            ldsm4(bl, sKVlB + off);
            mma_bf16(c[2*np  ], qhf[kt], bh[0], bh[1]);
            mma_bf16(c[2*np  ], qhf[kt], bl[0], bl[1]);
            mma_bf16(c[2*np  ], qlf[kt], bh[0], bh[1]);
            mma_bf16(c[2*np+1], qhf[kt], bh[2], bh[3]);
            mma_bf16(c[2*np+1], qhf[kt], bl[2], bl[3]);
            mma_bf16(c[2*np+1], qlf[kt], bh[2], bh[3]);
        }
    }
    __syncthreads();

    #pragma unroll
    for (int i = tid; i < 2048; i += 128) {
        int r = i >> 3, cc = (i & 7) * 16;
        cpa16(sKVhB + (uint32_t)(r * 144 + cc), Vh + (size_t)r * KVE + cc / 2);
        cpa16(sKVlB + (uint32_t)(r * 144 + cc), Vl + (size_t)r * KVE + cc / 2);
    }
    CP_COMMIT;

    float mx0 = -1e30f, mx1 = -1e30f;
    #pragma unroll
    for (int nt = 0; nt < 32; nt++) {
        mx0 = fmaxf(mx0, fmaxf(c[nt][0], c[nt][1]));
        mx1 = fmaxf(mx1, fmaxf(c[nt][2], c[nt][3]));
    }
    mx0 = fmaxf(mx0, __shfl_xor_sync(0xffffffffu, mx0, 1));
    mx0 = fmaxf(mx0, __shfl_xor_sync(0xffffffffu, mx0, 2));
    mx1 = fmaxf(mx1, __shfl_xor_sync(0xffffffffu, mx1, 1));
    mx1 = fmaxf(mx1, __shfl_xor_sync(0xffffffffu, mx1, 2));
    float s0 = 0.f, s1 = 0.f;
    #pragma unroll
    for (int nt = 0; nt < 32; nt++) {
        c[nt][0] = __expf(c[nt][0] - mx0); s0 += c[nt][0];
        c[nt][1] = __expf(c[nt][1] - mx0); s0 += c[nt][1];
        c[nt][2] = __expf(c[nt][2] - mx1); s1 += c[nt][2];
        c[nt][3] = __expf(c[nt][3] - mx1); s1 += c[nt][3];
    }
    s0 += __shfl_xor_sync(0xffffffffu, s0, 1);
    s0 += __shfl_xor_sync(0xffffffffu, s0, 2);
    s1 += __shfl_xor_sync(0xffffffffu, s1, 1);
    s1 += __shfl_xor_sync(0xffffffffu, s1, 2);
    float i0 = 1.0f / s0, i1 = 1.0f / s1;
    #pragma unroll
    for (int nt = 0; nt < 32; nt++) {
        c[nt][0] *= i0; c[nt][1] *= i0; c[nt][2] *= i1; c[nt][3] *= i1;
    }
    CP_WAIT0;
    __syncthreads();

    float o[8][4];
    #pragma unroll
    for (int i = 0; i < 8; i++)
        #pragma unroll
        for (int j = 0; j < 4; j++) o[i][j] = 0.f;

    int vrow = (lane & 7) + (lane & 8);
    int vcb  = (lane & 16) >> 1;
    #pragma unroll
    for (int kt = 0; kt < 16; kt++) {
        uint32_t phi[4], plo[4];
        phi[0] = pack_hl(c[2*kt  ][0], c[2*kt  ][1], plo[0]);
        phi[1] = pack_hl(c[2*kt  ][2], c[2*kt  ][3], plo[1]);
        phi[2] = pack_hl(c[2*kt+1][0], c[2*kt+1][1], plo[2]);
        phi[3] = pack_hl(c[2*kt+1][2], c[2*kt+1][3], plo[3]);
        #pragma unroll
        for (int dp = 0; dp < 4; dp++) {
            uint32_t off = (uint32_t)(((kt * 16 + vrow) * 72 + dp * 16 + vcb) * 2);
            uint32_t bh[4], bl[4];
            ldsm4t(bh, sKVhB + off);
            ldsm4t(bl, sKVlB + off);
            mma_bf16(o[2*dp  ], phi, bh[0], bh[1]);
            mma_bf16(o[2*dp  ], phi, bl[0], bl[1]);
            mma_bf16(o[2*dp  ], plo, bh[0], bh[1]);
            mma_bf16(o[2*dp+1], phi, bh[2], bh[3]);
            mma_bf16(o[2*dp+1], phi, bl[2], bl[3]);
            mma_bf16(o[2*dp+1], plo, bh[2], bh[3]);
        }
    }

    float* Ob = g_att + ((size_t)(b * N_ + qt * 64 + w * 16 + (lane >> 2))) * D_ + qh * HD;
    #pragma unroll
    for (int nt = 0; nt < 8; nt++) {
        int col = nt * 8 + (lane & 3) * 2;
        *(float2*)(Ob + col)          = make_float2(o[nt][0], o[nt][1]);
        *(float2*)(Ob + 8 * D_ + col) = make_float2(o[nt][2], o[nt][3]);
    }
}

// ---------------- launch ----------------------------------------------------
extern "C" void kernel_launch(void* const* d_in, const int* in_sizes, int n_in,
                              void* d_out, int out_size) {
    const float* x  = (const float*)d_in[0];
    const float* y  = (const float*)d_in[1];
    const float* wq = (const float*)d_in[2];
    const float* wk = (const float*)d_in[3];
    const float* wv = (const float*)d_in[4];
    const float* wo = (const float*)d_in[5];
    const float* gamma = (const float*)d_in[6];
    const float* beta  = (const float*)d_in[7];
    float* out = (float*)d_out;

    cudaFuncSetAttribute(attn_mma_kernel,
                         cudaFuncAttributeMaxDynamicSharedMemorySize, ATT_SMEM);
    cudaFuncSetAttribute(gemm_qkv_kernel, cudaFuncAttributeMaxDynamicSharedMemorySize, G_SMEM4);
    cudaFuncSetAttribute(gemm_o_kernel,   cudaFuncAttributeMaxDynamicSharedMemorySize, G_SMEM4);

    absmean_all_kernel<<<dim3(256, 4), 256>>>(wq, wk, wv, wo);
    reduce_kernel<<<4, 256>>>();
    wquant_all_kernel<<<dim3(512, 4), 256>>>(wq, wk, wv, wo);

    act_quant_kernel<<<(B_ * N_ + B_ * S_) / 8, 256>>>(x, y);

    gemm_qkv_kernel<<<1280, 256, G_SMEM4>>>();

    attn_mma_kernel<<<B_ * HQ * (N_ / 64), 128, ATT_SMEM>>>();

    ln_quant_kernel<<<B_ * N_ / 8, 256>>>(gamma, beta);
    gemm_o_kernel<<<dim3(8, 128), 256, G_SMEM4>>>(out);
}